// round 12
// baseline (speedup 1.0000x reference)
#include <cuda_runtime.h>
#include <cuda_bf16.h>
#include <cuda_fp16.h>
#include <math.h>
#include <stdint.h>

#define QLEN   1024
#define BSZ    4
#define DMODEL 1024
#define NHEAD  16
#define GHEADS 2
#define DHEAD  64
#define QKD    128
#define QKVOUT 1280
#define MROWS  4096
#define SCALE  0.125f
#define LN_EPS 1e-5f

// ---------------- scratch (device globals; no allocations allowed) ----------
__device__ float g_wheads[MROWS * QKVOUT];
__device__ float g_rk[QLEN * QKD];
__device__ float g_AC[BSZ * GHEADS * QLEN * QLEN];
__device__ float g_BD[BSZ * GHEADS * QLEN * QLEN];
__device__ float g_avec[MROWS * DMODEL];
__device__ float g_x[MROWS * DMODEL];

__device__ __nv_bfloat16 g_bfA_hi[MROWS * DMODEL];
__device__ __nv_bfloat16 g_bfA_lo[MROWS * DMODEL];
__device__ __nv_bfloat16 g_bfB_hi[QKVOUT * DMODEL];
__device__ __nv_bfloat16 g_bfB_lo[QKVOUT * DMODEL];

// normalized probabilities, single fp16: [b][h][i][j]  (134 MB)
__device__ __half g_P[BSZ * NHEAD * QLEN * QLEN];
// V transposed [b][h][d][j], fp16 hi/lo (exact two-term representation)
__device__ __half g_Vthi[BSZ * NHEAD * DHEAD * QLEN];
__device__ __half g_Vtlo[BSZ * NHEAD * DHEAD * QLEN];

// acbd operands, bf16 hi/lo, contiguous [bg][row][64]
__device__ __nv_bfloat16 g_Qrw_hi[8 * QLEN * DHEAD];
__device__ __nv_bfloat16 g_Qrw_lo[8 * QLEN * DHEAD];
__device__ __nv_bfloat16 g_Qrr_hi[8 * QLEN * DHEAD];
__device__ __nv_bfloat16 g_Qrr_lo[8 * QLEN * DHEAD];
__device__ __nv_bfloat16 g_Kw_hi[8 * QLEN * DHEAD];
__device__ __nv_bfloat16 g_Kw_lo[8 * QLEN * DHEAD];
__device__ __nv_bfloat16 g_rkw_hi[2 * QLEN * DHEAD];
__device__ __nv_bfloat16 g_rkw_lo[2 * QLEN * DHEAD];

// ---------------- helpers ----------------------------------------------------
__device__ __forceinline__ uint32_t smem_u32(const void* p) {
    uint32_t a;
    asm("{ .reg .u64 t; cvta.to.shared.u64 t, %1; cvt.u32.u64 %0, t; }"
        : "=r"(a) : "l"(p));
    return a;
}
__device__ __forceinline__ void ldm4(uint32_t* r, uint32_t addr) {
    asm volatile("ldmatrix.sync.aligned.m8n8.x4.shared.b16 {%0,%1,%2,%3}, [%4];"
                 : "=r"(r[0]), "=r"(r[1]), "=r"(r[2]), "=r"(r[3]) : "r"(addr));
}
__device__ __forceinline__ void mma16816(float* c, const uint32_t* a,
                                         uint32_t b0, uint32_t b1) {
    asm volatile(
        "mma.sync.aligned.m16n8k16.row.col.f32.bf16.bf16.f32 "
        "{%0,%1,%2,%3}, {%4,%5,%6,%7}, {%8,%9}, {%0,%1,%2,%3};"
        : "+f"(c[0]), "+f"(c[1]), "+f"(c[2]), "+f"(c[3])
        : "r"(a[0]), "r"(a[1]), "r"(a[2]), "r"(a[3]), "r"(b0), "r"(b1));
}
__device__ __forceinline__ void mma16816h(float* c, const uint32_t* a,
                                          uint32_t b0, uint32_t b1) {
    asm volatile(
        "mma.sync.aligned.m16n8k16.row.col.f32.f16.f16.f32 "
        "{%0,%1,%2,%3}, {%4,%5,%6,%7}, {%8,%9}, {%0,%1,%2,%3};"
        : "+f"(c[0]), "+f"(c[1]), "+f"(c[2]), "+f"(c[3])
        : "r"(a[0]), "r"(a[1]), "r"(a[2]), "r"(a[3]), "r"(b0), "r"(b1));
}
__device__ __forceinline__ void cp16(uint32_t saddr, const void* gaddr) {
    asm volatile("cp.async.cg.shared.global [%0], [%1], 16;\n"
                 :: "r"(saddr), "l"(gaddr) : "memory");
}

// ---------------- fp32 -> bf16 hi/lo split ----------------------------------
__global__ void __launch_bounds__(256) cvt_split(
    const float* __restrict__ x, __nv_bfloat16* __restrict__ hi,
    __nv_bfloat16* __restrict__ lo, int n)
{
    int i = (blockIdx.x * 256 + threadIdx.x) * 4;
    if (i >= n) return;
    float4 v = *(const float4*)(x + i);
    union { __nv_bfloat16 b[4]; uint2 u; } H, L;
    H.b[0] = __float2bfloat16_rn(v.x);
    H.b[1] = __float2bfloat16_rn(v.y);
    H.b[2] = __float2bfloat16_rn(v.z);
    H.b[3] = __float2bfloat16_rn(v.w);
    L.b[0] = __float2bfloat16_rn(v.x - __bfloat162float(H.b[0]));
    L.b[1] = __float2bfloat16_rn(v.y - __bfloat162float(H.b[1]));
    L.b[2] = __float2bfloat16_rn(v.z - __bfloat162float(H.b[2]));
    L.b[3] = __float2bfloat16_rn(v.w - __bfloat162float(H.b[3]));
    *(uint2*)(hi + i) = H.u;
    *(uint2*)(lo + i) = L.u;
}

// ---------------- HMMA split-bf16 NT GEMM, cp.async double-buffered ---------
#define LDSB  40
#define TILEE (128 * LDSB)
#define GEMM_SMEM (2 * 4 * TILEE * 2)

__global__ void __launch_bounds__(256) mma_gemm(
    const __nv_bfloat16* __restrict__ Ahi, const __nv_bfloat16* __restrict__ Alo,
    const __nv_bfloat16* __restrict__ Bhi, const __nv_bfloat16* __restrict__ Blo,
    const float* __restrict__ Dres, float* __restrict__ C, int N_, int K)
{
    extern __shared__ __nv_bfloat16 gsm[];
    const uint32_t sbase = smem_u32(gsm);

    const int t = threadIdx.x;
    const int warp = t >> 5, lane = t & 31;
    const int wm = warp >> 2, wn = warp & 3;
    const int m0 = blockIdx.y * 128, n0 = blockIdx.x * 128;

    float acc[4][4][4];
    #pragma unroll
    for (int i = 0; i < 4; i++)
        #pragma unroll
        for (int j = 0; j < 4; j++)
            #pragma unroll
            for (int u = 0; u < 4; u++) acc[i][j][u] = 0.f;

    const int lrow = t >> 2;
    const int lseg = (t & 3) * 8;

    const __nv_bfloat16* mat[4];
    mat[0] = Ahi + (size_t)m0 * K;
    mat[1] = Alo + (size_t)m0 * K;
    mat[2] = Bhi + (size_t)n0 * K;
    mat[3] = Blo + (size_t)n0 * K;

    const uint32_t so_b = ((uint32_t)lrow * LDSB + lseg) * 2;
    const uint32_t so_b2 = so_b + (uint32_t)64 * LDSB * 2;

    const uint32_t a_lane =
        ((uint32_t)(wm * 64 + (lane & 15)) * LDSB + (lane >> 4) * 8) * 2;
    const uint32_t b_lane =
        ((uint32_t)(wn * 32 + (lane & 7) + (lane >> 4) * 8) * LDSB +
         ((lane >> 3) & 1) * 8) * 2;

    const int NCH = K >> 5;

    #pragma unroll
    for (int mi = 0; mi < 4; mi++) {
        const uint32_t mb = sbase + (uint32_t)mi * TILEE * 2;
        cp16(mb + so_b,  mat[mi] + (size_t)lrow * K + lseg);
        cp16(mb + so_b2, mat[mi] + (size_t)(lrow + 64) * K + lseg);
    }
    asm volatile("cp.async.commit_group;\n");

    for (int c = 0; c < NCH; c++) {
        if (c + 1 < NCH) {
            const int k0 = (c + 1) << 5;
            const uint32_t stoff = (uint32_t)(((c + 1) & 1) * 4) * TILEE * 2;
            #pragma unroll
            for (int mi = 0; mi < 4; mi++) {
                const uint32_t mb = sbase + stoff + (uint32_t)mi * TILEE * 2;
                cp16(mb + so_b,  mat[mi] + (size_t)lrow * K + k0 + lseg);
                cp16(mb + so_b2, mat[mi] + (size_t)(lrow + 64) * K + k0 + lseg);
            }
            asm volatile("cp.async.commit_group;\n");
            asm volatile("cp.async.wait_group 1;\n");
        } else {
            asm volatile("cp.async.wait_group 0;\n");
        }
        __syncthreads();

        const uint32_t stoff = (uint32_t)((c & 1) * 4) * TILEE * 2;
        const uint32_t bAh = sbase + stoff;
        const uint32_t bAl = bAh + TILEE * 2;
        const uint32_t bBh = bAl + TILEE * 2;
        const uint32_t bBl = bBh + TILEE * 2;

        #pragma unroll
        for (int s = 0; s < 2; s++) {
            const uint32_t ko = s * 32;
            uint32_t ah[4][4], al[4][4], bh[2][4], bl[2][4];
            #pragma unroll
            for (int mf = 0; mf < 4; mf++) {
                ldm4(ah[mf], bAh + a_lane + mf * 1280 + ko);
                ldm4(al[mf], bAl + a_lane + mf * 1280 + ko);
            }
            #pragma unroll
            for (int np = 0; np < 2; np++) {
                ldm4(bh[np], bBh + b_lane + np * 1280 + ko);
                ldm4(bl[np], bBl + b_lane + np * 1280 + ko);
            }
            #pragma unroll
            for (int mf = 0; mf < 4; mf++) {
                #pragma unroll
                for (int nf = 0; nf < 4; nf++) {
                    const int np = nf >> 1, h = (nf & 1) * 2;
                    mma16816(acc[mf][nf], ah[mf], bh[np][h], bh[np][h + 1]);
                    mma16816(acc[mf][nf], ah[mf], bl[np][h], bl[np][h + 1]);
                    mma16816(acc[mf][nf], al[mf], bh[np][h], bh[np][h + 1]);
                }
            }
        }
        __syncthreads();
    }

    const int crow0 = m0 + wm * 64 + (lane >> 2);
    const int ccol0 = n0 + wn * 32 + (lane & 3) * 2;
    #pragma unroll
    for (int mf = 0; mf < 4; mf++) {
        #pragma unroll
        for (int nf = 0; nf < 4; nf++) {
            const int gr = crow0 + mf * 16;
            const int gc = ccol0 + nf * 8;
            float2 v0 = make_float2(acc[mf][nf][0], acc[mf][nf][1]);
            float2 v1 = make_float2(acc[mf][nf][2], acc[mf][nf][3]);
            if (Dres) {
                float2 d0 = *(const float2*)(Dres + (size_t)gr * N_ + gc);
                float2 d1 = *(const float2*)(Dres + (size_t)(gr + 8) * N_ + gc);
                v0.x += d0.x; v0.y += d0.y;
                v1.x += d1.x; v1.y += d1.y;
            }
            *(float2*)(C + (size_t)gr * N_ + gc) = v0;
            *(float2*)(C + (size_t)(gr + 8) * N_ + gc) = v1;
        }
    }
}

// ---------------- acbd operand conversion -----------------------------------
// Builds (Q+rwb), (Q+rrb), K as bf16 hi/lo in [bg][row][64] layout.
__global__ void __launch_bounds__(512) cvt_qk(
    const float* __restrict__ wheads,
    const float* __restrict__ rwb, const float* __restrict__ rrb,
    __nv_bfloat16* __restrict__ qrwh, __nv_bfloat16* __restrict__ qrwl,
    __nv_bfloat16* __restrict__ qrrh, __nv_bfloat16* __restrict__ qrrl,
    __nv_bfloat16* __restrict__ kh,   __nv_bfloat16* __restrict__ kl)
{
    const int i = blockIdx.x;
    const int t = threadIdx.x;
    const int bg = t >> 6, d = t & 63;
    const int b = bg >> 1, g = bg & 1;
    const size_t src = (size_t)(i * BSZ + b) * QKVOUT + g * 64 + d;
    const size_t dst = (size_t)bg * QLEN * 64 + (size_t)i * 64 + d;

    float q = wheads[src];
    float k = wheads[src + QKD];
    float q0 = q + rwb[g * 64 + d];
    float q1 = q + rrb[g * 64 + d];

    __nv_bfloat16 h;
    h = __float2bfloat16_rn(q0); qrwh[dst] = h;
    qrwl[dst] = __float2bfloat16_rn(q0 - __bfloat162float(h));
    h = __float2bfloat16_rn(q1); qrrh[dst] = h;
    qrrl[dst] = __float2bfloat16_rn(q1 - __bfloat162float(h));
    h = __float2bfloat16_rn(k);  kh[dst] = h;
    kl[dst] = __float2bfloat16_rn(k - __bfloat162float(h));
}

__global__ void __launch_bounds__(128) cvt_rk(
    const float* __restrict__ rk,
    __nv_bfloat16* __restrict__ rkh, __nv_bfloat16* __restrict__ rkl)
{
    const int i = blockIdx.x;
    const int t = threadIdx.x;            // g*64+d
    float v = rk[(size_t)i * QKD + t];
    const int g = t >> 6, d = t & 63;
    const size_t dst = (size_t)g * QLEN * 64 + (size_t)i * 64 + d;
    __nv_bfloat16 h = __float2bfloat16_rn(v);
    rkh[dst] = h;
    rkl[dst] = __float2bfloat16_rn(v - __bfloat162float(h));
}

// ---------------- acbd HMMA: AC/BD = A @ B^T, K=64 --------------------------
// grid (8, 8, 16): z = mode*8 + bg.
__global__ void __launch_bounds__(256) acbd_mma(
    const __nv_bfloat16* __restrict__ Qrwh, const __nv_bfloat16* __restrict__ Qrwl,
    const __nv_bfloat16* __restrict__ Qrrh, const __nv_bfloat16* __restrict__ Qrrl,
    const __nv_bfloat16* __restrict__ Kwh,  const __nv_bfloat16* __restrict__ Kwl,
    const __nv_bfloat16* __restrict__ rkwh, const __nv_bfloat16* __restrict__ rkwl,
    float* __restrict__ ACo, float* __restrict__ BDo)
{
    extern __shared__ __nv_bfloat16 gsm[];
    const uint32_t sbase = smem_u32(gsm);

    const int z = blockIdx.z;
    const int mode = z >> 3, bg = z & 7, g = bg & 1;
    const size_t qoff = (size_t)bg * QLEN * 64;

    const __nv_bfloat16* mat[4];
    mat[0] = (mode ? Qrrh : Qrwh) + qoff;
    mat[1] = (mode ? Qrrl : Qrwl) + qoff;
    mat[2] = mode ? (rkwh + (size_t)g * QLEN * 64) : (Kwh + qoff);
    mat[3] = mode ? (rkwl + (size_t)g * QLEN * 64) : (Kwl + qoff);
    float* C = (mode ? BDo : ACo) + (size_t)bg * QLEN * QLEN;

    const int t = threadIdx.x;
    const int warp = t >> 5, lane = t & 31;
    const int wm = warp >> 2, wn = warp & 3;
    const int m0 = blockIdx.y * 128, n0 = blockIdx.x * 128;
    const int K = 64;

    float acc[4][4][4];
    #pragma unroll
    for (int i = 0; i < 4; i++)
        #pragma unroll
        for (int j = 0; j < 4; j++)
            #pragma unroll
            for (int u = 0; u < 4; u++) acc[i][j][u] = 0.f;

    mat[0] += (size_t)m0 * K;
    mat[1] += (size_t)m0 * K;
    mat[2] += (size_t)n0 * K;
    mat[3] += (size_t)n0 * K;

    const int lrow = t >> 2;
    const int lseg = (t & 3) * 8;
    const uint32_t so_b = ((uint32_t)lrow * LDSB + lseg) * 2;
    const uint32_t so_b2 = so_b + (uint32_t)64 * LDSB * 2;

    const uint32_t a_lane =
        ((uint32_t)(wm * 64 + (lane & 15)) * LDSB + (lane >> 4) * 8) * 2;
    const uint32_t b_lane =
        ((uint32_t)(wn * 32 + (lane & 7) + (lane >> 4) * 8) * LDSB +
         ((lane >> 3) & 1) * 8) * 2;

    #pragma unroll
    for (int mi = 0; mi < 4; mi++) {
        const uint32_t mb = sbase + (uint32_t)mi * TILEE * 2;
        cp16(mb + so_b,  mat[mi] + (size_t)lrow * K + lseg);
        cp16(mb + so_b2, mat[mi] + (size_t)(lrow + 64) * K + lseg);
    }
    asm volatile("cp.async.commit_group;\n");

    #pragma unroll
    for (int c = 0; c < 2; c++) {
        if (c == 0) {
            const int k0 = 32;
            const uint32_t stoff = (uint32_t)4 * TILEE * 2;
            #pragma unroll
            for (int mi = 0; mi < 4; mi++) {
                const uint32_t mb = sbase + stoff + (uint32_t)mi * TILEE * 2;
                cp16(mb + so_b,  mat[mi] + (size_t)lrow * K + k0 + lseg);
                cp16(mb + so_b2, mat[mi] + (size_t)(lrow + 64) * K + k0 + lseg);
            }
            asm volatile("cp.async.commit_group;\n");
            asm volatile("cp.async.wait_group 1;\n");
        } else {
            asm volatile("cp.async.wait_group 0;\n");
        }
        __syncthreads();

        const uint32_t stoff = (uint32_t)((c & 1) * 4) * TILEE * 2;
        const uint32_t bAh = sbase + stoff;
        const uint32_t bAl = bAh + TILEE * 2;
        const uint32_t bBh = bAl + TILEE * 2;
        const uint32_t bBl = bBh + TILEE * 2;

        #pragma unroll
        for (int s = 0; s < 2; s++) {
            const uint32_t ko = s * 32;
            uint32_t ah[4][4], al[4][4], bh[2][4], bl[2][4];
            #pragma unroll
            for (int mf = 0; mf < 4; mf++) {
                ldm4(ah[mf], bAh + a_lane + mf * 1280 + ko);
                ldm4(al[mf], bAl + a_lane + mf * 1280 + ko);
            }
            #pragma unroll
            for (int np = 0; np < 2; np++) {
                ldm4(bh[np], bBh + b_lane + np * 1280 + ko);
                ldm4(bl[np], bBl + b_lane + np * 1280 + ko);
            }
            #pragma unroll
            for (int mf = 0; mf < 4; mf++) {
                #pragma unroll
                for (int nf = 0; nf < 4; nf++) {
                    const int np = nf >> 1, h = (nf & 1) * 2;
                    mma16816(acc[mf][nf], ah[mf], bh[np][h], bh[np][h + 1]);
                    mma16816(acc[mf][nf], ah[mf], bl[np][h], bl[np][h + 1]);
                    mma16816(acc[mf][nf], al[mf], bh[np][h], bh[np][h + 1]);
                }
            }
        }
        __syncthreads();
    }

    const int crow0 = m0 + wm * 64 + (lane >> 2);
    const int ccol0 = n0 + wn * 32 + (lane & 3) * 2;
    #pragma unroll
    for (int mf = 0; mf < 4; mf++) {
        #pragma unroll
        for (int nf = 0; nf < 4; nf++) {
            const int gr = crow0 + mf * 16;
            const int gc = ccol0 + nf * 8;
            *(float2*)(C + (size_t)gr * QLEN + gc) =
                make_float2(acc[mf][nf][0], acc[mf][nf][1]);
            *(float2*)(C + (size_t)(gr + 8) * QLEN + gc) =
                make_float2(acc[mf][nf][2], acc[mf][nf][3]);
        }
    }
}

// ---------------- score + rel_shift + mask + softmax -> fp16 P --------------
#define SC_SMEM (16 * 1024 * 4)

__global__ void __launch_bounds__(256) score_kernel(
    const float* __restrict__ AC, const float* __restrict__ BD,
    const float* __restrict__ masks, const float* __restrict__ mproj,
    __half* __restrict__ P)
{
    extern __shared__ float S[];              // [16][1024]
    const int i = blockIdx.x, b = blockIdx.y;
    const int t = threadIdx.x;
    const int warp = t >> 5, lane = t & 31;

    float mp0[16], mp1[16], mp2[16];
    #pragma unroll
    for (int h = 0; h < 16; h++) {
        mp0[h] = mproj[h];
        mp1[h] = mproj[16 + h];
        mp2[h] = mproj[32 + h];
    }

    const float* ac0r = AC + ((size_t)(b * 2 + 0) * QLEN + i) * QLEN;
    const float* ac1r = AC + ((size_t)(b * 2 + 1) * QLEN + i) * QLEN;
    const float* bd0b = BD + (size_t)(b * 2 + 0) * QLEN * QLEN;
    const float* bd1b = BD + (size_t)(b * 2 + 1) * QLEN * QLEN;

    #pragma unroll
    for (int k = 0; k < 4; k++) {
        const int j = t + k * 256;
        float ac0 = ac0r[j], ac1 = ac1r[j];
        unsigned s  = (unsigned)(i + 1) * 1024u + (unsigned)j;
        unsigned i2 = s / 1025u;
        unsigned j2 = s - i2 * 1025u;
        float bd0 = 0.f, bd1 = 0.f;
        if (j2) {
            bd0 = bd0b[(size_t)i2 * QLEN + (j2 - 1u)];
            bd1 = bd1b[(size_t)i2 * QLEN + (j2 - 1u)];
        }
        const float* mr = masks + ((size_t)i * QLEN + j) * 3;
        float m0 = mr[0], m1 = mr[1], m2 = mr[2];
        float base0 = (ac0 + bd0) * SCALE;
        float base1 = (ac1 + bd1) * SCALE;
        #pragma unroll
        for (int h = 0; h < 8; h++) {
            float mw = m0 * mp0[h] + m1 * mp1[h] + m2 * mp2[h];
            S[h * 1024 + j] = base0 * mw;
        }
        #pragma unroll
        for (int h = 8; h < 16; h++) {
            float mw = m0 * mp0[h] + m1 * mp1[h] + m2 * mp2[h];
            S[h * 1024 + j] = base1 * mw;
        }
    }
    __syncthreads();

    #pragma unroll
    for (int hh = 0; hh < 2; hh++) {
        const int h = warp * 2 + hh;
        float* Sh = S + h * 1024;
        float mx = -1e30f;
        #pragma unroll 8
        for (int j = lane; j < 1024; j += 32) mx = fmaxf(mx, Sh[j]);
        #pragma unroll
        for (int o = 16; o > 0; o >>= 1)
            mx = fmaxf(mx, __shfl_xor_sync(0xffffffffu, mx, o));
        float sum = 0.f;
        #pragma unroll 8
        for (int j = lane; j < 1024; j += 32) {
            float e = __expf(Sh[j] - mx);
            Sh[j] = e;
            sum += e;
        }
        #pragma unroll
        for (int o = 16; o > 0; o >>= 1)
            sum += __shfl_xor_sync(0xffffffffu, sum, o);
        const float inv = 1.f / sum;
        __half* ph = P + ((size_t)(b * 16 + h) * QLEN + i) * QLEN;
        #pragma unroll 8
        for (int j = lane; j < 1024; j += 32)
            ph[j] = __float2half_rn(Sh[j] * inv);
    }
}

// ---------------- V transpose-convert: wheads -> Vt[b][h][d][j] fp16 --------
__global__ void __launch_bounds__(256) cvt_vt(
    const float* __restrict__ wheads,
    __half* __restrict__ Vthi, __half* __restrict__ Vtlo)
{
    __shared__ float sm[64 * 33];
    const int bh = blockIdx.y;
    const int b = bh >> 4, h = bh & 15;
    const int j0 = blockIdx.x * 32;
    const int t = threadIdx.x;

    #pragma unroll
    for (int k = 0; k < 8; k++) {
        int idx = t + k * 256;
        int j = idx >> 6, d = idx & 63;
        sm[d * 33 + j] = wheads[(size_t)(j0 + j) * (BSZ * QKVOUT) +
                                b * QKVOUT + 2 * QKD + h * 64 + d];
    }
    __syncthreads();
    #pragma unroll
    for (int k = 0; k < 8; k++) {
        int idx = t + k * 256;
        int d = idx >> 5, j = idx & 31;
        float v = sm[d * 33 + j];
        __half hi = __float2half_rn(v);
        size_t o = ((size_t)(bh * 64 + d)) * QLEN + j0 + j;
        Vthi[o] = hi;
        Vtlo[o] = __float2half_rn(v - __half2float(hi));
    }
}

// ---------------- PV GEMM: avec[i,d] = sum_j P[i,j] * Vt[d,j] ---------------
// P single fp16, V fp16 hi/lo -> 2-term. BM=128, BN=64, BK=32.
#define PV_TILEA (128 * LDSB)
#define PV_TILEB (64 * LDSB)
#define PV_STAGE (PV_TILEA + 2 * PV_TILEB)
#define PV_SMEM  (2 * PV_STAGE * 2)

__global__ void __launch_bounds__(256) pv_gemm(
    const __half* __restrict__ P,
    const __half* __restrict__ Vthi, const __half* __restrict__ Vtlo,
    float* __restrict__ avec)
{
    extern __shared__ __half psm[];
    const uint32_t sbase = smem_u32(psm);
    const int bh = blockIdx.y;
    const int b = bh >> 4, h = bh & 15;
    const int i0 = blockIdx.x * 128;
    const int t = threadIdx.x;
    const int warp = t >> 5, lane = t & 31;
    const int wm = warp >> 1, wn = warp & 1;

    float acc[2][4][4];
    #pragma unroll
    for (int i = 0; i < 2; i++)
        #pragma unroll
        for (int j = 0; j < 4; j++)
            #pragma unroll
            for (int u = 0; u < 4; u++) acc[i][j][u] = 0.f;

    const __half* pA = P + ((size_t)bh * QLEN + i0) * QLEN;
    const __half* pB[2];
    pB[0] = Vthi + (size_t)bh * 64 * QLEN;
    pB[1] = Vtlo + (size_t)bh * 64 * QLEN;

    const int arow = t >> 1;
    const int aoff = (t & 1) * 16;
    const int vrow = (t & 127) >> 1;
    const int voff = (t & 1) * 16;

    const uint32_t a_lane =
        ((uint32_t)(wm * 32 + (lane & 15)) * LDSB + (lane >> 4) * 8) * 2;
    const uint32_t b_lane =
        ((uint32_t)(wn * 32 + (lane & 7) + (lane >> 4) * 8) * LDSB +
         ((lane >> 3) & 1) * 8) * 2;

    // prologue stage 0
    {
        const uint32_t so = ((uint32_t)arow * LDSB + aoff) * 2;
        cp16(sbase + so,      pA + (size_t)arow * QLEN + aoff);
        cp16(sbase + so + 16, pA + (size_t)arow * QLEN + aoff + 8);
        if (t < 128) {
            #pragma unroll
            for (int m = 0; m < 2; m++) {
                const uint32_t mb = sbase +
                    (uint32_t)(PV_TILEA + m * PV_TILEB) * 2;
                const uint32_t sv = ((uint32_t)vrow * LDSB + voff) * 2;
                cp16(mb + sv,      pB[m] + (size_t)vrow * QLEN + voff);
                cp16(mb + sv + 16, pB[m] + (size_t)vrow * QLEN + voff + 8);
            }
        }
        asm volatile("cp.async.commit_group;\n");
    }

    const int NCH = QLEN >> 5;
    for (int c = 0; c < NCH; c++) {
        if (c + 1 < NCH) {
            const int k0 = (c + 1) << 5;
            const uint32_t stoff = (uint32_t)(((c + 1) & 1) * PV_STAGE) * 2;
            const uint32_t so = ((uint32_t)arow * LDSB + aoff) * 2;
            cp16(sbase + stoff + so,      pA + (size_t)arow * QLEN + k0 + aoff);
            cp16(sbase + stoff + so + 16, pA + (size_t)arow * QLEN + k0 + aoff + 8);
            if (t < 128) {
                #pragma unroll
                for (int m = 0; m < 2; m++) {
                    const uint32_t mb = sbase + stoff +
                        (uint32_t)(PV_TILEA + m * PV_TILEB) * 2;
                    const uint32_t sv = ((uint32_t)vrow * LDSB + voff) * 2;
                    cp16(mb + sv,      pB[m] + (size_t)vrow * QLEN + k0 + voff);
                    cp16(mb + sv + 16, pB[m] + (size_t)vrow * QLEN + k0 + voff + 8);
                }
            }
            asm volatile("cp.async.commit_group;\n");
            asm volatile("cp.async.wait_group 1;\n");
        } else {
            asm volatile("cp.async.wait_group 0;\n");
        }
        __syncthreads();

        const uint32_t stoff = (uint32_t)((c & 1) * PV_STAGE) * 2;
        const uint32_t bP  = sbase + stoff;
        const uint32_t bVh = bP + (uint32_t)PV_TILEA * 2;
        const uint32_t bVl = bVh + (uint32_t)PV_TILEB * 2;

        #pragma unroll
        for (int s = 0; s < 2; s++) {
            const uint32_t ko = s * 32;
            uint32_t ap[2][4], vh[2][4], vl[2][4];
            #pragma unroll
            for (int mf = 0; mf < 2; mf++)
                ldm4(ap[mf], bP + a_lane + mf * 1280 + ko);
            #pragma unroll
            for (int np = 0; np < 2; np++) {
                ldm4(vh[np], bVh + b_lane + np * 1280 + ko);
                ldm4(vl[np], bVl + b_lane + np * 1280 + ko);
            }
            #pragma unroll
            for (int mf = 0; mf < 2; mf++) {
                #pragma unroll
                for (int nf = 0; nf < 4; nf++) {
                    const int np = nf >> 1, hb = (nf & 1) * 2;
                    mma16816h(acc[mf][nf], ap[mf], vh[np][hb], vh[np][hb + 1]);
                    mma16816h(acc[mf][nf], ap[mf], vl[np][hb], vl[np][hb + 1]);
                }
            }
        }
        __syncthreads();
    }

    const int rloc0 = wm * 32 + (lane >> 2);
    const int col0  = wn * 32 + (lane & 3) * 2;
    #pragma unroll
    for (int mf = 0; mf < 2; mf++) {
        #pragma unroll
        for (int nf = 0; nf < 4; nf++) {
            const int gr0 = i0 + rloc0 + mf * 16;
            const int gc  = col0 + nf * 8;
            float* o0 = avec + ((size_t)(gr0 * BSZ + b) * NHEAD + h) * 64 + gc;
            float* o1 = avec + ((size_t)((gr0 + 8) * BSZ + b) * NHEAD + h) * 64 + gc;
            *(float2*)o0 = make_float2(acc[mf][nf][0], acc[mf][nf][1]);
            *(float2*)o1 = make_float2(acc[mf][nf][2], acc[mf][nf][3]);
        }
    }
}

// ---------------- LayerNorm --------------------------------------------------
__global__ void __launch_bounds__(256) ln_kernel(
    const float* __restrict__ X, const float* __restrict__ gamma,
    const float* __restrict__ beta, float* __restrict__ out)
{
    const int row = blockIdx.x;
    const int t = threadIdx.x;
    const float4* x4 = (const float4*)(X + (size_t)row * DMODEL);
    float4 v = x4[t];
    float s  = v.x + v.y + v.z + v.w;
    float sq = v.x * v.x + v.y * v.y + v.z * v.z + v.w * v.w;
    #pragma unroll
    for (int o = 16; o > 0; o >>= 1) {
        s  += __shfl_xor_sync(0xffffffffu, s,  o);
        sq += __shfl_xor_sync(0xffffffffu, sq, o);
    }
    __shared__ float ssum[8], ssq[8];
    __shared__ float smu, srstd;
    if ((t & 31) == 0) { ssum[t >> 5] = s; ssq[t >> 5] = sq; }
    __syncthreads();
    if (t == 0) {
        float ts = 0.f, tq = 0.f;
        #pragma unroll
        for (int k = 0; k < 8; k++) { ts += ssum[k]; tq += ssq[k]; }
        float mu = ts * (1.f / DMODEL);
        float var = tq * (1.f / DMODEL) - mu * mu;
        smu = mu;
        srstd = rsqrtf(var + LN_EPS);
    }
    __syncthreads();
    float mu = smu, rstd = srstd;
    float4 gm = ((const float4*)gamma)[t];
    float4 bt = ((const float4*)beta)[t];
    float4 o;
    o.x = (v.x - mu) * rstd * gm.x + bt.x;
    o.y = (v.y - mu) * rstd * gm.y + bt.y;
    o.z = (v.z - mu) * rstd * gm.z + bt.z;
    o.w = (v.w - mu) * rstd * gm.w + bt.w;
    ((float4*)(out + (size_t)row * DMODEL))[t] = o;
}

// ---------------- launch ----------------------------------------------------
extern "C" void kernel_launch(void* const* d_in, const int* in_sizes, int n_in,
                              void* d_out, int out_size)
{
    const float* w     = (const float*)d_in[0];
    const float* r     = (const float*)d_in[1];
    const float* rwb   = (const float*)d_in[2];
    const float* rrb   = (const float*)d_in[3];
    const float* masks = (const float*)d_in[4];
    const float* Wqkv  = (const float*)d_in[5];
    const float* Wr    = (const float*)d_in[6];
    const float* mproj = (const float*)d_in[7];
    const float* Wo    = (const float*)d_in[8];
    const float* gamma = (const float*)d_in[9];
    const float* beta  = (const float*)d_in[10];
    float* out = (float*)d_out;

    float *wheads, *rkp, *acp, *bdp, *avp, *xp;
    cudaGetSymbolAddress((void**)&wheads, g_wheads);
    cudaGetSymbolAddress((void**)&rkp,    g_rk);
    cudaGetSymbolAddress((void**)&acp,    g_AC);
    cudaGetSymbolAddress((void**)&bdp,    g_BD);
    cudaGetSymbolAddress((void**)&avp,    g_avec);
    cudaGetSymbolAddress((void**)&xp,     g_x);

    __nv_bfloat16 *Ah, *Al, *Bh, *Bl;
    cudaGetSymbolAddress((void**)&Ah,  g_bfA_hi);
    cudaGetSymbolAddress((void**)&Al,  g_bfA_lo);
    cudaGetSymbolAddress((void**)&Bh,  g_bfB_hi);
    cudaGetSymbolAddress((void**)&Bl,  g_bfB_lo);

    __half *Pp, *Vth, *Vtl;
    cudaGetSymbolAddress((void**)&Pp,  g_P);
    cudaGetSymbolAddress((void**)&Vth, g_Vthi);
    cudaGetSymbolAddress((void**)&Vtl, g_Vtlo);

    __nv_bfloat16 *qrwh, *qrwl, *qrrh, *qrrl, *kwh, *kwl, *rkwh, *rkwl;
    cudaGetSymbolAddress((void**)&qrwh, g_Qrw_hi);
    cudaGetSymbolAddress((void**)&qrwl, g_Qrw_lo);
    cudaGetSymbolAddress((void**)&qrrh, g_Qrr_hi);
    cudaGetSymbolAddress((void**)&qrrl, g_Qrr_lo);
    cudaGetSymbolAddress((void**)&kwh,  g_Kw_hi);
    cudaGetSymbolAddress((void**)&kwl,  g_Kw_lo);
    cudaGetSymbolAddress((void**)&rkwh, g_rkw_hi);
    cudaGetSymbolAddress((void**)&rkwl, g_rkw_lo);

    cudaFuncSetAttribute(mma_gemm,
                         cudaFuncAttributeMaxDynamicSharedMemorySize, GEMM_SMEM);
    cudaFuncSetAttribute(acbd_mma,
                         cudaFuncAttributeMaxDynamicSharedMemorySize, GEMM_SMEM);
    cudaFuncSetAttribute(score_kernel,
                         cudaFuncAttributeMaxDynamicSharedMemorySize, SC_SMEM);
    cudaFuncSetAttribute(pv_gemm,
                         cudaFuncAttributeMaxDynamicSharedMemorySize, PV_SMEM);

    // 1) w_heads = w @ W_qkv^T
    cvt_split<<<(MROWS * DMODEL) / 1024, 256>>>(w, Ah, Al, MROWS * DMODEL);
    cvt_split<<<(QKVOUT * DMODEL) / 1024, 256>>>(Wqkv, Bh, Bl, QKVOUT * DMODEL);
    mma_gemm<<<dim3(QKVOUT / 128, MROWS / 128), 256, GEMM_SMEM>>>(
        Ah, Al, Bh, Bl, nullptr, wheads, QKVOUT, DMODEL);

    // 2) r_head_k = r @ W_r^T
    cvt_split<<<(QLEN * DMODEL) / 1024, 256>>>(r, Ah, Al, QLEN * DMODEL);
    cvt_split<<<(QKD * DMODEL) / 1024, 256>>>(Wr, Bh, Bl, QKD * DMODEL);
    mma_gemm<<<dim3(QKD / 128, QLEN / 128), 256, GEMM_SMEM>>>(
        Ah, Al, Bh, Bl, nullptr, rkp, QKD, DMODEL);

    // 3) AC, BD via HMMA
    cvt_qk<<<QLEN, 512>>>(wheads, rwb, rrb, qrwh, qrwl, qrrh, qrrl, kwh, kwl);
    cvt_rk<<<QLEN, 128>>>(rkp, rkwh, rkwl);
    acbd_mma<<<dim3(8, 8, 16), 256, GEMM_SMEM>>>(
        qrwh, qrwl, qrrh, qrrl, kwh, kwl, rkwh, rkwl, acp, bdp);

    // 4a) scores + softmax -> fp16 P
    score_kernel<<<dim3(QLEN, BSZ), 256, SC_SMEM>>>(
        acp, bdp, masks, mproj, Pp);

    // 4b) V transpose-convert (fp16 hi/lo)
    cvt_vt<<<dim3(QLEN / 32, BSZ * NHEAD), 256>>>(wheads, Vth, Vtl);

    // 4c) PV GEMM -> avec
    pv_gemm<<<dim3(QLEN / 128, BSZ * NHEAD), 256, PV_SMEM>>>(
        Pp, Vth, Vtl, avp);

    // 5) x = attn_vec @ W_o^T + w
    cvt_split<<<(MROWS * DMODEL) / 1024, 256>>>(avp, Ah, Al, MROWS * DMODEL);
    cvt_split<<<(DMODEL * DMODEL) / 1024, 256>>>(Wo, Bh, Bl, DMODEL * DMODEL);
    mma_gemm<<<dim3(DMODEL / 128, MROWS / 128), 256, GEMM_SMEM>>>(
        Ah, Al, Bh, Bl, w, xp, DMODEL, DMODEL);

    // 6) LayerNorm -> out
    ln_kernel<<<MROWS, 256>>>(xp, gamma, beta, out);
}

// round 13
// speedup vs baseline: 1.6504x; 1.6504x over previous
#include <cuda_runtime.h>
#include <cuda_bf16.h>
#include <cuda_fp16.h>
#include <math.h>
#include <stdint.h>

#define QLEN   1024
#define BSZ    4
#define DMODEL 1024
#define NHEAD  16
#define GHEADS 2
#define DHEAD  64
#define QKD    128
#define QKVOUT 1280
#define MROWS  4096
#define SCALE  0.125f
#define LN_EPS 1e-5f

// ---------------- scratch (device globals; no allocations allowed) ----------
__device__ float g_wheads[MROWS * QKVOUT];
__device__ float g_rk[QLEN * QKD];
__device__ float g_AC[BSZ * GHEADS * QLEN * QLEN];
__device__ float g_BD[BSZ * GHEADS * QLEN * QLEN];
__device__ float g_avec[MROWS * DMODEL];
__device__ float g_x[MROWS * DMODEL];

__device__ __nv_bfloat16 g_bfA_hi[MROWS * DMODEL];
__device__ __nv_bfloat16 g_bfA_lo[MROWS * DMODEL];
__device__ __nv_bfloat16 g_bfB_hi[QKVOUT * DMODEL];
__device__ __nv_bfloat16 g_bfB_lo[QKVOUT * DMODEL];

// normalized probabilities, single fp16: [b][h][i][j]  (134 MB)
__device__ __half g_P[BSZ * NHEAD * QLEN * QLEN];
// V transposed [b][h][d][j], fp16 hi/lo
__device__ __half g_Vthi[BSZ * NHEAD * DHEAD * QLEN];
__device__ __half g_Vtlo[BSZ * NHEAD * DHEAD * QLEN];

// ---------------- helpers ----------------------------------------------------
__device__ __forceinline__ uint32_t smem_u32(const void* p) {
    uint32_t a;
    asm("{ .reg .u64 t; cvta.to.shared.u64 t, %1; cvt.u32.u64 %0, t; }"
        : "=r"(a) : "l"(p));
    return a;
}
__device__ __forceinline__ void ldm4(uint32_t* r, uint32_t addr) {
    asm volatile("ldmatrix.sync.aligned.m8n8.x4.shared.b16 {%0,%1,%2,%3}, [%4];"
                 : "=r"(r[0]), "=r"(r[1]), "=r"(r[2]), "=r"(r[3]) : "r"(addr));
}
__device__ __forceinline__ void mma16816(float* c, const uint32_t* a,
                                         uint32_t b0, uint32_t b1) {
    asm volatile(
        "mma.sync.aligned.m16n8k16.row.col.f32.bf16.bf16.f32 "
        "{%0,%1,%2,%3}, {%4,%5,%6,%7}, {%8,%9}, {%0,%1,%2,%3};"
        : "+f"(c[0]), "+f"(c[1]), "+f"(c[2]), "+f"(c[3])
        : "r"(a[0]), "r"(a[1]), "r"(a[2]), "r"(a[3]), "r"(b0), "r"(b1));
}
__device__ __forceinline__ void mma16816h(float* c, const uint32_t* a,
                                          uint32_t b0, uint32_t b1) {
    asm volatile(
        "mma.sync.aligned.m16n8k16.row.col.f32.f16.f16.f32 "
        "{%0,%1,%2,%3}, {%4,%5,%6,%7}, {%8,%9}, {%0,%1,%2,%3};"
        : "+f"(c[0]), "+f"(c[1]), "+f"(c[2]), "+f"(c[3])
        : "r"(a[0]), "r"(a[1]), "r"(a[2]), "r"(a[3]), "r"(b0), "r"(b1));
}
__device__ __forceinline__ void cp16(uint32_t saddr, const void* gaddr) {
    asm volatile("cp.async.cg.shared.global [%0], [%1], 16;\n"
                 :: "r"(saddr), "l"(gaddr) : "memory");
}

// ---------------- fp32 -> bf16 hi/lo split ----------------------------------
__global__ void __launch_bounds__(256) cvt_split(
    const float* __restrict__ x, __nv_bfloat16* __restrict__ hi,
    __nv_bfloat16* __restrict__ lo, int n)
{
    int i = (blockIdx.x * 256 + threadIdx.x) * 4;
    if (i >= n) return;
    float4 v = *(const float4*)(x + i);
    union { __nv_bfloat16 b[4]; uint2 u; } H, L;
    H.b[0] = __float2bfloat16_rn(v.x);
    H.b[1] = __float2bfloat16_rn(v.y);
    H.b[2] = __float2bfloat16_rn(v.z);
    H.b[3] = __float2bfloat16_rn(v.w);
    L.b[0] = __float2bfloat16_rn(v.x - __bfloat162float(H.b[0]));
    L.b[1] = __float2bfloat16_rn(v.y - __bfloat162float(H.b[1]));
    L.b[2] = __float2bfloat16_rn(v.z - __bfloat162float(H.b[2]));
    L.b[3] = __float2bfloat16_rn(v.w - __bfloat162float(H.b[3]));
    *(uint2*)(hi + i) = H.u;
    *(uint2*)(lo + i) = L.u;
}

// ---------------- HMMA split-bf16 NT GEMM, cp.async double-buffered ---------
#define LDSB  40
#define TILEE (128 * LDSB)
#define GEMM_SMEM (2 * 4 * TILEE * 2)

__global__ void __launch_bounds__(256) mma_gemm(
    const __nv_bfloat16* __restrict__ Ahi, const __nv_bfloat16* __restrict__ Alo,
    const __nv_bfloat16* __restrict__ Bhi, const __nv_bfloat16* __restrict__ Blo,
    const float* __restrict__ Dres, float* __restrict__ C, int N_, int K)
{
    extern __shared__ __nv_bfloat16 gsm[];
    const uint32_t sbase = smem_u32(gsm);

    const int t = threadIdx.x;
    const int warp = t >> 5, lane = t & 31;
    const int wm = warp >> 2, wn = warp & 3;
    const int m0 = blockIdx.y * 128, n0 = blockIdx.x * 128;

    float acc[4][4][4];
    #pragma unroll
    for (int i = 0; i < 4; i++)
        #pragma unroll
        for (int j = 0; j < 4; j++)
            #pragma unroll
            for (int u = 0; u < 4; u++) acc[i][j][u] = 0.f;

    const int lrow = t >> 2;
    const int lseg = (t & 3) * 8;

    const __nv_bfloat16* mat[4];
    mat[0] = Ahi + (size_t)m0 * K;
    mat[1] = Alo + (size_t)m0 * K;
    mat[2] = Bhi + (size_t)n0 * K;
    mat[3] = Blo + (size_t)n0 * K;

    const uint32_t so_b = ((uint32_t)lrow * LDSB + lseg) * 2;
    const uint32_t so_b2 = so_b + (uint32_t)64 * LDSB * 2;

    const uint32_t a_lane =
        ((uint32_t)(wm * 64 + (lane & 15)) * LDSB + (lane >> 4) * 8) * 2;
    const uint32_t b_lane =
        ((uint32_t)(wn * 32 + (lane & 7) + (lane >> 4) * 8) * LDSB +
         ((lane >> 3) & 1) * 8) * 2;

    const int NCH = K >> 5;

    #pragma unroll
    for (int mi = 0; mi < 4; mi++) {
        const uint32_t mb = sbase + (uint32_t)mi * TILEE * 2;
        cp16(mb + so_b,  mat[mi] + (size_t)lrow * K + lseg);
        cp16(mb + so_b2, mat[mi] + (size_t)(lrow + 64) * K + lseg);
    }
    asm volatile("cp.async.commit_group;\n");

    for (int c = 0; c < NCH; c++) {
        if (c + 1 < NCH) {
            const int k0 = (c + 1) << 5;
            const uint32_t stoff = (uint32_t)(((c + 1) & 1) * 4) * TILEE * 2;
            #pragma unroll
            for (int mi = 0; mi < 4; mi++) {
                const uint32_t mb = sbase + stoff + (uint32_t)mi * TILEE * 2;
                cp16(mb + so_b,  mat[mi] + (size_t)lrow * K + k0 + lseg);
                cp16(mb + so_b2, mat[mi] + (size_t)(lrow + 64) * K + k0 + lseg);
            }
            asm volatile("cp.async.commit_group;\n");
            asm volatile("cp.async.wait_group 1;\n");
        } else {
            asm volatile("cp.async.wait_group 0;\n");
        }
        __syncthreads();

        const uint32_t stoff = (uint32_t)((c & 1) * 4) * TILEE * 2;
        const uint32_t bAh = sbase + stoff;
        const uint32_t bAl = bAh + TILEE * 2;
        const uint32_t bBh = bAl + TILEE * 2;
        const uint32_t bBl = bBh + TILEE * 2;

        #pragma unroll
        for (int s = 0; s < 2; s++) {
            const uint32_t ko = s * 32;
            uint32_t ah[4][4], al[4][4], bh[2][4], bl[2][4];
            #pragma unroll
            for (int mf = 0; mf < 4; mf++) {
                ldm4(ah[mf], bAh + a_lane + mf * 1280 + ko);
                ldm4(al[mf], bAl + a_lane + mf * 1280 + ko);
            }
            #pragma unroll
            for (int np = 0; np < 2; np++) {
                ldm4(bh[np], bBh + b_lane + np * 1280 + ko);
                ldm4(bl[np], bBl + b_lane + np * 1280 + ko);
            }
            #pragma unroll
            for (int mf = 0; mf < 4; mf++) {
                #pragma unroll
                for (int nf = 0; nf < 4; nf++) {
                    const int np = nf >> 1, h = (nf & 1) * 2;
                    mma16816(acc[mf][nf], ah[mf], bh[np][h], bh[np][h + 1]);
                    mma16816(acc[mf][nf], ah[mf], bl[np][h], bl[np][h + 1]);
                    mma16816(acc[mf][nf], al[mf], bh[np][h], bh[np][h + 1]);
                }
            }
        }
        __syncthreads();
    }

    const int crow0 = m0 + wm * 64 + (lane >> 2);
    const int ccol0 = n0 + wn * 32 + (lane & 3) * 2;
    #pragma unroll
    for (int mf = 0; mf < 4; mf++) {
        #pragma unroll
        for (int nf = 0; nf < 4; nf++) {
            const int gr = crow0 + mf * 16;
            const int gc = ccol0 + nf * 8;
            float2 v0 = make_float2(acc[mf][nf][0], acc[mf][nf][1]);
            float2 v1 = make_float2(acc[mf][nf][2], acc[mf][nf][3]);
            if (Dres) {
                float2 d0 = *(const float2*)(Dres + (size_t)gr * N_ + gc);
                float2 d1 = *(const float2*)(Dres + (size_t)(gr + 8) * N_ + gc);
                v0.x += d0.x; v0.y += d0.y;
                v1.x += d1.x; v1.y += d1.y;
            }
            *(float2*)(C + (size_t)gr * N_ + gc) = v0;
            *(float2*)(C + (size_t)(gr + 8) * N_ + gc) = v1;
        }
    }
}

// ---------------- AC / BD batched GEMM (K=64, fp32 FFMA), merged launch -----
// grid (8, 8, 16): z = mode*8 + bg.
__global__ void __launch_bounds__(256) acbd_kernel(
    const float* __restrict__ wheads, const float* __restrict__ rk,
    const float* __restrict__ rwb, const float* __restrict__ rrb,
    float* __restrict__ ACo, float* __restrict__ BDo)
{
    __shared__ float As[16][132];
    __shared__ float Bs[16][132];
    const int z = blockIdx.z;
    const int mode = z >> 3, bg = z & 7;
    const int b = bg >> 1, g = bg & 1;
    const int bx = blockIdx.x, by = blockIdx.y;
    const int t  = threadIdx.x;
    const int tx = t & 15, ty = t >> 4;

    const float* Aoff = wheads + b * QKVOUT + g * 64;
    const float* Boff = mode ? (rk + g * 64)
                             : (wheads + b * QKVOUT + QKD + g * 64);
    const int lda = BSZ * QKVOUT;
    const int ldb = mode ? QKD : (BSZ * QKVOUT);
    const float* bb = (mode ? rrb : rwb) + g * 64;

    float acc[8][8];
    #pragma unroll
    for (int i = 0; i < 8; i++)
        #pragma unroll
        for (int j = 0; j < 8; j++) acc[i][j] = 0.f;

    const int lrow = t >> 2;
    const int lk4  = (t & 3) * 4;

    for (int k0 = 0; k0 < 64; k0 += 16) {
        float4 bias4 = *(const float4*)(bb + k0 + lk4);
        #pragma unroll
        for (int rr = 0; rr < 2; rr++) {
            int m = lrow + rr * 64;
            int gm = by * 128 + m;
            float4 a = *(const float4*)(Aoff + (size_t)gm * lda + k0 + lk4);
            As[lk4 + 0][m] = a.x + bias4.x; As[lk4 + 1][m] = a.y + bias4.y;
            As[lk4 + 2][m] = a.z + bias4.z; As[lk4 + 3][m] = a.w + bias4.w;
            int gn = bx * 128 + m;
            float4 bv = *(const float4*)(Boff + (size_t)gn * ldb + k0 + lk4);
            Bs[lk4 + 0][m] = bv.x; Bs[lk4 + 1][m] = bv.y;
            Bs[lk4 + 2][m] = bv.z; Bs[lk4 + 3][m] = bv.w;
        }
        __syncthreads();
        #pragma unroll
        for (int kk = 0; kk < 16; kk++) {
            float ar[8], br[8];
            #pragma unroll
            for (int u = 0; u < 8; u++) ar[u] = As[kk][ty * 8 + u];
            #pragma unroll
            for (int u = 0; u < 8; u++) br[u] = Bs[kk][tx * 8 + u];
            #pragma unroll
            for (int i = 0; i < 8; i++)
                #pragma unroll
                for (int j = 0; j < 8; j++) acc[i][j] += ar[i] * br[j];
        }
        __syncthreads();
    }
    float* C = (mode ? BDo : ACo) + (size_t)bg * QLEN * QLEN;
    const int mbase = by * 128 + ty * 8;
    const int nbase = bx * 128 + tx * 8;
    #pragma unroll
    for (int i = 0; i < 8; i++) {
        size_t roff = (size_t)(mbase + i) * QLEN + nbase;
        #pragma unroll
        for (int j0 = 0; j0 < 8; j0 += 4) {
            float4 o;
            o.x = acc[i][j0 + 0]; o.y = acc[i][j0 + 1];
            o.z = acc[i][j0 + 2]; o.w = acc[i][j0 + 3];
            *(float4*)(C + roff + j0) = o;
        }
    }
}

// ---------------- score + rel_shift + mask + softmax -> fp16 P --------------
#define SC_SMEM (16 * 1024 * 4)

__global__ void __launch_bounds__(256) score_kernel(
    const float* __restrict__ AC, const float* __restrict__ BD,
    const float* __restrict__ masks, const float* __restrict__ mproj,
    __half* __restrict__ P)
{
    extern __shared__ float S[];              // [16][1024]
    const int i = blockIdx.x, b = blockIdx.y;
    const int t = threadIdx.x;
    const int warp = t >> 5, lane = t & 31;

    float mp0[16], mp1[16], mp2[16];
    #pragma unroll
    for (int h = 0; h < 16; h++) {
        mp0[h] = mproj[h];
        mp1[h] = mproj[16 + h];
        mp2[h] = mproj[32 + h];
    }

    const float* ac0r = AC + ((size_t)(b * 2 + 0) * QLEN + i) * QLEN;
    const float* ac1r = AC + ((size_t)(b * 2 + 1) * QLEN + i) * QLEN;
    const float* bd0b = BD + (size_t)(b * 2 + 0) * QLEN * QLEN;
    const float* bd1b = BD + (size_t)(b * 2 + 1) * QLEN * QLEN;

    #pragma unroll
    for (int k = 0; k < 4; k++) {
        const int j = t + k * 256;
        float ac0 = ac0r[j], ac1 = ac1r[j];
        unsigned s  = (unsigned)(i + 1) * 1024u + (unsigned)j;
        unsigned i2 = s / 1025u;
        unsigned j2 = s - i2 * 1025u;
        float bd0 = 0.f, bd1 = 0.f;
        if (j2) {
            bd0 = bd0b[(size_t)i2 * QLEN + (j2 - 1u)];
            bd1 = bd1b[(size_t)i2 * QLEN + (j2 - 1u)];
        }
        const float* mr = masks + ((size_t)i * QLEN + j) * 3;
        float m0 = mr[0], m1 = mr[1], m2 = mr[2];
        float base0 = (ac0 + bd0) * SCALE;
        float base1 = (ac1 + bd1) * SCALE;
        #pragma unroll
        for (int h = 0; h < 8; h++) {
            float mw = m0 * mp0[h] + m1 * mp1[h] + m2 * mp2[h];
            S[h * 1024 + j] = base0 * mw;
        }
        #pragma unroll
        for (int h = 8; h < 16; h++) {
            float mw = m0 * mp0[h] + m1 * mp1[h] + m2 * mp2[h];
            S[h * 1024 + j] = base1 * mw;
        }
    }
    __syncthreads();

    #pragma unroll
    for (int hh = 0; hh < 2; hh++) {
        const int h = warp * 2 + hh;
        float* Sh = S + h * 1024;
        float mx = -1e30f;
        #pragma unroll 8
        for (int j = lane; j < 1024; j += 32) mx = fmaxf(mx, Sh[j]);
        #pragma unroll
        for (int o = 16; o > 0; o >>= 1)
            mx = fmaxf(mx, __shfl_xor_sync(0xffffffffu, mx, o));
        float sum = 0.f;
        #pragma unroll 8
        for (int j = lane; j < 1024; j += 32) {
            float e = __expf(Sh[j] - mx);
            Sh[j] = e;
            sum += e;
        }
        #pragma unroll
        for (int o = 16; o > 0; o >>= 1)
            sum += __shfl_xor_sync(0xffffffffu, sum, o);
        const float inv = 1.f / sum;
        __half* ph = P + ((size_t)(b * 16 + h) * QLEN + i) * QLEN;
        #pragma unroll 8
        for (int j = lane; j < 1024; j += 32)
            ph[j] = __float2half_rn(Sh[j] * inv);
    }
}

// ---------------- V transpose-convert: wheads -> Vt[b][h][d][j] fp16 --------
__global__ void __launch_bounds__(256) cvt_vt(
    const float* __restrict__ wheads,
    __half* __restrict__ Vthi, __half* __restrict__ Vtlo)
{
    __shared__ float sm[64 * 33];
    const int bh = blockIdx.y;
    const int b = bh >> 4, h = bh & 15;
    const int j0 = blockIdx.x * 32;
    const int t = threadIdx.x;

    #pragma unroll
    for (int k = 0; k < 8; k++) {
        int idx = t + k * 256;
        int j = idx >> 6, d = idx & 63;
        sm[d * 33 + j] = wheads[(size_t)(j0 + j) * (BSZ * QKVOUT) +
                                b * QKVOUT + 2 * QKD + h * 64 + d];
    }
    __syncthreads();
    #pragma unroll
    for (int k = 0; k < 8; k++) {
        int idx = t + k * 256;
        int d = idx >> 5, j = idx & 31;
        float v = sm[d * 33 + j];
        __half hi = __float2half_rn(v);
        size_t o = ((size_t)(bh * 64 + d)) * QLEN + j0 + j;
        Vthi[o] = hi;
        Vtlo[o] = __float2half_rn(v - __half2float(hi));
    }
}

// ---------------- PV GEMM: avec[i,d] = sum_j P[i,j] * Vt[d,j] ---------------
#define PV_TILEA (128 * LDSB)
#define PV_TILEB (64 * LDSB)
#define PV_STAGE (PV_TILEA + 2 * PV_TILEB)
#define PV_SMEM  (2 * PV_STAGE * 2)

__global__ void __launch_bounds__(256) pv_gemm(
    const __half* __restrict__ P,
    const __half* __restrict__ Vthi, const __half* __restrict__ Vtlo,
    float* __restrict__ avec)
{
    extern __shared__ __half psm[];
    const uint32_t sbase = smem_u32(psm);
    const int bh = blockIdx.y;
    const int b = bh >> 4, h = bh & 15;
    const int i0 = blockIdx.x * 128;
    const int t = threadIdx.x;
    const int warp = t >> 5, lane = t & 31;
    const int wm = warp >> 1, wn = warp & 1;

    float acc[2][4][4];
    #pragma unroll
    for (int i = 0; i < 2; i++)
        #pragma unroll
        for (int j = 0; j < 4; j++)
            #pragma unroll
            for (int u = 0; u < 4; u++) acc[i][j][u] = 0.f;

    const __half* pA = P + ((size_t)bh * QLEN + i0) * QLEN;
    const __half* pB[2];
    pB[0] = Vthi + (size_t)bh * 64 * QLEN;
    pB[1] = Vtlo + (size_t)bh * 64 * QLEN;

    const int arow = t >> 1;
    const int aoff = (t & 1) * 16;
    const int vrow = (t & 127) >> 1;
    const int voff = (t & 1) * 16;

    const uint32_t a_lane =
        ((uint32_t)(wm * 32 + (lane & 15)) * LDSB + (lane >> 4) * 8) * 2;
    const uint32_t b_lane =
        ((uint32_t)(wn * 32 + (lane & 7) + (lane >> 4) * 8) * LDSB +
         ((lane >> 3) & 1) * 8) * 2;

    // prologue stage 0
    {
        const uint32_t so = ((uint32_t)arow * LDSB + aoff) * 2;
        cp16(sbase + so,      pA + (size_t)arow * QLEN + aoff);
        cp16(sbase + so + 16, pA + (size_t)arow * QLEN + aoff + 8);
        if (t < 128) {
            #pragma unroll
            for (int m = 0; m < 2; m++) {
                const uint32_t mb = sbase +
                    (uint32_t)(PV_TILEA + m * PV_TILEB) * 2;
                const uint32_t sv = ((uint32_t)vrow * LDSB + voff) * 2;
                cp16(mb + sv,      pB[m] + (size_t)vrow * QLEN + voff);
                cp16(mb + sv + 16, pB[m] + (size_t)vrow * QLEN + voff + 8);
            }
        }
        asm volatile("cp.async.commit_group;\n");
    }

    const int NCH = QLEN >> 5;
    for (int c = 0; c < NCH; c++) {
        if (c + 1 < NCH) {
            const int k0 = (c + 1) << 5;
            const uint32_t stoff = (uint32_t)(((c + 1) & 1) * PV_STAGE) * 2;
            const uint32_t so = ((uint32_t)arow * LDSB + aoff) * 2;
            cp16(sbase + stoff + so,      pA + (size_t)arow * QLEN + k0 + aoff);
            cp16(sbase + stoff + so + 16, pA + (size_t)arow * QLEN + k0 + aoff + 8);
            if (t < 128) {
                #pragma unroll
                for (int m = 0; m < 2; m++) {
                    const uint32_t mb = sbase + stoff +
                        (uint32_t)(PV_TILEA + m * PV_TILEB) * 2;
                    const uint32_t sv = ((uint32_t)vrow * LDSB + voff) * 2;
                    cp16(mb + sv,      pB[m] + (size_t)vrow * QLEN + k0 + voff);
                    cp16(mb + sv + 16, pB[m] + (size_t)vrow * QLEN + k0 + voff + 8);
                }
            }
            asm volatile("cp.async.commit_group;\n");
            asm volatile("cp.async.wait_group 1;\n");
        } else {
            asm volatile("cp.async.wait_group 0;\n");
        }
        __syncthreads();

        const uint32_t stoff = (uint32_t)((c & 1) * PV_STAGE) * 2;
        const uint32_t bP  = sbase + stoff;
        const uint32_t bVh = bP + (uint32_t)PV_TILEA * 2;
        const uint32_t bVl = bVh + (uint32_t)PV_TILEB * 2;

        #pragma unroll
        for (int s = 0; s < 2; s++) {
            const uint32_t ko = s * 32;
            uint32_t ap[2][4], vh[2][4], vl[2][4];
            #pragma unroll
            for (int mf = 0; mf < 2; mf++)
                ldm4(ap[mf], bP + a_lane + mf * 1280 + ko);
            #pragma unroll
            for (int np = 0; np < 2; np++) {
                ldm4(vh[np], bVh + b_lane + np * 1280 + ko);
                ldm4(vl[np], bVl + b_lane + np * 1280 + ko);
            }
            #pragma unroll
            for (int mf = 0; mf < 2; mf++) {
                #pragma unroll
                for (int nf = 0; nf < 4; nf++) {
                    const int np = nf >> 1, hb = (nf & 1) * 2;
                    mma16816h(acc[mf][nf], ap[mf], vh[np][hb], vh[np][hb + 1]);
                    mma16816h(acc[mf][nf], ap[mf], vl[np][hb], vl[np][hb + 1]);
                }
            }
        }
        __syncthreads();
    }

    const int rloc0 = wm * 32 + (lane >> 2);
    const int col0  = wn * 32 + (lane & 3) * 2;
    #pragma unroll
    for (int mf = 0; mf < 2; mf++) {
        #pragma unroll
        for (int nf = 0; nf < 4; nf++) {
            const int gr0 = i0 + rloc0 + mf * 16;
            const int gc  = col0 + nf * 8;
            float* o0 = avec + ((size_t)(gr0 * BSZ + b) * NHEAD + h) * 64 + gc;
            float* o1 = avec + ((size_t)((gr0 + 8) * BSZ + b) * NHEAD + h) * 64 + gc;
            *(float2*)o0 = make_float2(acc[mf][nf][0], acc[mf][nf][1]);
            *(float2*)o1 = make_float2(acc[mf][nf][2], acc[mf][nf][3]);
        }
    }
}

// ---------------- LayerNorm --------------------------------------------------
__global__ void __launch_bounds__(256) ln_kernel(
    const float* __restrict__ X, const float* __restrict__ gamma,
    const float* __restrict__ beta, float* __restrict__ out)
{
    const int row = blockIdx.x;
    const int t = threadIdx.x;
    const float4* x4 = (const float4*)(X + (size_t)row * DMODEL);
    float4 v = x4[t];
    float s  = v.x + v.y + v.z + v.w;
    float sq = v.x * v.x + v.y * v.y + v.z * v.z + v.w * v.w;
    #pragma unroll
    for (int o = 16; o > 0; o >>= 1) {
        s  += __shfl_xor_sync(0xffffffffu, s,  o);
        sq += __shfl_xor_sync(0xffffffffu, sq, o);
    }
    __shared__ float ssum[8], ssq[8];
    __shared__ float smu, srstd;
    if ((t & 31) == 0) { ssum[t >> 5] = s; ssq[t >> 5] = sq; }
    __syncthreads();
    if (t == 0) {
        float ts = 0.f, tq = 0.f;
        #pragma unroll
        for (int k = 0; k < 8; k++) { ts += ssum[k]; tq += ssq[k]; }
        float mu = ts * (1.f / DMODEL);
        float var = tq * (1.f / DMODEL) - mu * mu;
        smu = mu;
        srstd = rsqrtf(var + LN_EPS);
    }
    __syncthreads();
    float mu = smu, rstd = srstd;
    float4 gm = ((const float4*)gamma)[t];
    float4 bt = ((const float4*)beta)[t];
    float4 o;
    o.x = (v.x - mu) * rstd * gm.x + bt.x;
    o.y = (v.y - mu) * rstd * gm.y + bt.y;
    o.z = (v.z - mu) * rstd * gm.z + bt.z;
    o.w = (v.w - mu) * rstd * gm.w + bt.w;
    ((float4*)(out + (size_t)row * DMODEL))[t] = o;
}

// ---------------- launch ----------------------------------------------------
extern "C" void kernel_launch(void* const* d_in, const int* in_sizes, int n_in,
                              void* d_out, int out_size)
{
    const float* w     = (const float*)d_in[0];
    const float* r     = (const float*)d_in[1];
    const float* rwb   = (const float*)d_in[2];
    const float* rrb   = (const float*)d_in[3];
    const float* masks = (const float*)d_in[4];
    const float* Wqkv  = (const float*)d_in[5];
    const float* Wr    = (const float*)d_in[6];
    const float* mproj = (const float*)d_in[7];
    const float* Wo    = (const float*)d_in[8];
    const float* gamma = (const float*)d_in[9];
    const float* beta  = (const float*)d_in[10];
    float* out = (float*)d_out;

    float *wheads, *rkp, *acp, *bdp, *avp, *xp;
    cudaGetSymbolAddress((void**)&wheads, g_wheads);
    cudaGetSymbolAddress((void**)&rkp,    g_rk);
    cudaGetSymbolAddress((void**)&acp,    g_AC);
    cudaGetSymbolAddress((void**)&bdp,    g_BD);
    cudaGetSymbolAddress((void**)&avp,    g_avec);
    cudaGetSymbolAddress((void**)&xp,     g_x);

    __nv_bfloat16 *Ah, *Al, *Bh, *Bl;
    cudaGetSymbolAddress((void**)&Ah,  g_bfA_hi);
    cudaGetSymbolAddress((void**)&Al,  g_bfA_lo);
    cudaGetSymbolAddress((void**)&Bh,  g_bfB_hi);
    cudaGetSymbolAddress((void**)&Bl,  g_bfB_lo);

    __half *Pp, *Vth, *Vtl;
    cudaGetSymbolAddress((void**)&Pp,  g_P);
    cudaGetSymbolAddress((void**)&Vth, g_Vthi);
    cudaGetSymbolAddress((void**)&Vtl, g_Vtlo);

    cudaFuncSetAttribute(mma_gemm,
                         cudaFuncAttributeMaxDynamicSharedMemorySize, GEMM_SMEM);
    cudaFuncSetAttribute(score_kernel,
                         cudaFuncAttributeMaxDynamicSharedMemorySize, SC_SMEM);
    cudaFuncSetAttribute(pv_gemm,
                         cudaFuncAttributeMaxDynamicSharedMemorySize, PV_SMEM);

    // 1) w_heads = w @ W_qkv^T
    cvt_split<<<(MROWS * DMODEL) / 1024, 256>>>(w, Ah, Al, MROWS * DMODEL);
    cvt_split<<<(QKVOUT * DMODEL) / 1024, 256>>>(Wqkv, Bh, Bl, QKVOUT * DMODEL);
    mma_gemm<<<dim3(QKVOUT / 128, MROWS / 128), 256, GEMM_SMEM>>>(
        Ah, Al, Bh, Bl, nullptr, wheads, QKVOUT, DMODEL);

    // 2) r_head_k = r @ W_r^T
    cvt_split<<<(QLEN * DMODEL) / 1024, 256>>>(r, Ah, Al, QLEN * DMODEL);
    cvt_split<<<(QKD * DMODEL) / 1024, 256>>>(Wr, Bh, Bl, QKD * DMODEL);
    mma_gemm<<<dim3(QKD / 128, QLEN / 128), 256, GEMM_SMEM>>>(
        Ah, Al, Bh, Bl, nullptr, rkp, QKD, DMODEL);

    // 3) AC, BD (FFMA, merged single launch)
    acbd_kernel<<<dim3(8, 8, 16), 256>>>(wheads, rkp, rwb, rrb, acp, bdp);

    // 4a) scores + softmax -> fp16 P
    score_kernel<<<dim3(QLEN, BSZ), 256, SC_SMEM>>>(
        acp, bdp, masks, mproj, Pp);

    // 4b) V transpose-convert (fp16 hi/lo)
    cvt_vt<<<dim3(QLEN / 32, BSZ * NHEAD), 256>>>(wheads, Vth, Vtl);

    // 4c) PV GEMM -> avec
    pv_gemm<<<dim3(QLEN / 128, BSZ * NHEAD), 256, PV_SMEM>>>(
        Pp, Vth, Vtl, avp);

    // 5) x = attn_vec @ W_o^T + w
    cvt_split<<<(MROWS * DMODEL) / 1024, 256>>>(avp, Ah, Al, MROWS * DMODEL);
    cvt_split<<<(DMODEL * DMODEL) / 1024, 256>>>(Wo, Bh, Bl, DMODEL * DMODEL);
    mma_gemm<<<dim3(DMODEL / 128, MROWS / 128), 256, GEMM_SMEM>>>(
        Ah, Al, Bh, Bl, w, xp, DMODEL, DMODEL);

    // 6) LayerNorm -> out
    ln_kernel<<<MROWS, 256>>>(xp, gamma, beta, out);
}

// round 14
// speedup vs baseline: 2.0249x; 1.2269x over previous
#include <cuda_runtime.h>
#include <cuda_bf16.h>
#include <cuda_fp16.h>
#include <math.h>
#include <stdint.h>

#define QLEN   1024
#define BSZ    4
#define DMODEL 1024
#define NHEAD  16
#define GHEADS 2
#define DHEAD  64
#define QKD    128
#define QKVOUT 1280
#define MROWS  4096
#define SCALE  0.125f
#define LN_EPS 1e-5f

// ---------------- scratch (device globals; no allocations allowed) ----------
__device__ float g_wheads[MROWS * QKVOUT];
__device__ float g_rk[QLEN * QKD];
__device__ float g_AC[BSZ * GHEADS * QLEN * QLEN];
__device__ float g_BD[BSZ * GHEADS * QLEN * QLEN];
__device__ float g_avec[MROWS * DMODEL];
__device__ float g_x[MROWS * DMODEL];

// fp16 GEMM operands: A hi/lo (2-term exact), B single fp16
__device__ __half g_hA_hi[MROWS * DMODEL];
__device__ __half g_hA_lo[MROWS * DMODEL];
__device__ __half g_hB[QKVOUT * DMODEL];

// normalized probabilities, single fp16: [b][h][i][j]  (134 MB)
__device__ __half g_P[BSZ * NHEAD * QLEN * QLEN];
// V transposed [b][h][d][j], fp16 hi/lo
__device__ __half g_Vthi[BSZ * NHEAD * DHEAD * QLEN];
__device__ __half g_Vtlo[BSZ * NHEAD * DHEAD * QLEN];

// ---------------- helpers ----------------------------------------------------
__device__ __forceinline__ uint32_t smem_u32(const void* p) {
    uint32_t a;
    asm("{ .reg .u64 t; cvta.to.shared.u64 t, %1; cvt.u32.u64 %0, t; }"
        : "=r"(a) : "l"(p));
    return a;
}
__device__ __forceinline__ void ldm4(uint32_t* r, uint32_t addr) {
    asm volatile("ldmatrix.sync.aligned.m8n8.x4.shared.b16 {%0,%1,%2,%3}, [%4];"
                 : "=r"(r[0]), "=r"(r[1]), "=r"(r[2]), "=r"(r[3]) : "r"(addr));
}
__device__ __forceinline__ void mma16816h(float* c, const uint32_t* a,
                                          uint32_t b0, uint32_t b1) {
    asm volatile(
        "mma.sync.aligned.m16n8k16.row.col.f32.f16.f16.f32 "
        "{%0,%1,%2,%3}, {%4,%5,%6,%7}, {%8,%9}, {%0,%1,%2,%3};"
        : "+f"(c[0]), "+f"(c[1]), "+f"(c[2]), "+f"(c[3])
        : "r"(a[0]), "r"(a[1]), "r"(a[2]), "r"(a[3]), "r"(b0), "r"(b1));
}
__device__ __forceinline__ void cp16(uint32_t saddr, const void* gaddr) {
    asm volatile("cp.async.cg.shared.global [%0], [%1], 16;\n"
                 :: "r"(saddr), "l"(gaddr) : "memory");
}

// ---------------- fp32 -> fp16 hi/lo split -----------------------------------
__global__ void __launch_bounds__(256) cvt_split_h(
    const float* __restrict__ x, __half* __restrict__ hi,
    __half* __restrict__ lo, int n)
{
    int i = (blockIdx.x * 256 + threadIdx.x) * 4;
    if (i >= n) return;
    float4 v = *(const float4*)(x + i);
    union { __half b[4]; uint2 u; } H, L;
    H.b[0] = __float2half_rn(v.x);
    H.b[1] = __float2half_rn(v.y);
    H.b[2] = __float2half_rn(v.z);
    H.b[3] = __float2half_rn(v.w);
    L.b[0] = __float2half_rn(v.x - __half2float(H.b[0]));
    L.b[1] = __float2half_rn(v.y - __half2float(H.b[1]));
    L.b[2] = __float2half_rn(v.z - __half2float(H.b[2]));
    L.b[3] = __float2half_rn(v.w - __half2float(H.b[3]));
    *(uint2*)(hi + i) = H.u;
    *(uint2*)(lo + i) = L.u;
}

// ---------------- fp32 -> fp16 single ----------------------------------------
__global__ void __launch_bounds__(256) cvt_h(
    const float* __restrict__ x, __half* __restrict__ o, int n)
{
    int i = (blockIdx.x * 256 + threadIdx.x) * 4;
    if (i >= n) return;
    float4 v = *(const float4*)(x + i);
    union { __half b[4]; uint2 u; } H;
    H.b[0] = __float2half_rn(v.x);
    H.b[1] = __float2half_rn(v.y);
    H.b[2] = __float2half_rn(v.z);
    H.b[3] = __float2half_rn(v.w);
    *(uint2*)(o + i) = H.u;
}

// ---------------- fp16 2-term NT GEMM, cp.async double-buffered -------------
// C[m,n] = sum_k A[m,k]*B[n,k] (+Dres) with A = Ahi+Alo (exact), B fp16.
// BM=BN=128, BK=32. 256 threads = 8 warps (2m x 4n), warp tile 64x32.
#define LDSB  40
#define TILEE (128 * LDSB)
#define GEMM_SMEM (2 * 3 * TILEE * 2)      // 61440 bytes

__global__ void __launch_bounds__(256) mma_gemm(
    const __half* __restrict__ Ahi, const __half* __restrict__ Alo,
    const __half* __restrict__ B,
    const float* __restrict__ Dres, float* __restrict__ C, int N_, int K)
{
    extern __shared__ __half gsm[];
    const uint32_t sbase = smem_u32(gsm);

    const int t = threadIdx.x;
    const int warp = t >> 5, lane = t & 31;
    const int wm = warp >> 2, wn = warp & 3;
    const int m0 = blockIdx.y * 128, n0 = blockIdx.x * 128;

    float acc[4][4][4];
    #pragma unroll
    for (int i = 0; i < 4; i++)
        #pragma unroll
        for (int j = 0; j < 4; j++)
            #pragma unroll
            for (int u = 0; u < 4; u++) acc[i][j][u] = 0.f;

    const int lrow = t >> 2;
    const int lseg = (t & 3) * 8;

    const __half* mat[3];
    mat[0] = Ahi + (size_t)m0 * K;
    mat[1] = Alo + (size_t)m0 * K;
    mat[2] = B   + (size_t)n0 * K;

    const uint32_t so_b = ((uint32_t)lrow * LDSB + lseg) * 2;
    const uint32_t so_b2 = so_b + (uint32_t)64 * LDSB * 2;

    const uint32_t a_lane =
        ((uint32_t)(wm * 64 + (lane & 15)) * LDSB + (lane >> 4) * 8) * 2;
    const uint32_t b_lane =
        ((uint32_t)(wn * 32 + (lane & 7) + (lane >> 4) * 8) * LDSB +
         ((lane >> 3) & 1) * 8) * 2;

    const int NCH = K >> 5;

    #pragma unroll
    for (int mi = 0; mi < 3; mi++) {
        const uint32_t mb = sbase + (uint32_t)mi * TILEE * 2;
        cp16(mb + so_b,  mat[mi] + (size_t)lrow * K + lseg);
        cp16(mb + so_b2, mat[mi] + (size_t)(lrow + 64) * K + lseg);
    }
    asm volatile("cp.async.commit_group;\n");

    for (int c = 0; c < NCH; c++) {
        if (c + 1 < NCH) {
            const int k0 = (c + 1) << 5;
            const uint32_t stoff = (uint32_t)(((c + 1) & 1) * 3) * TILEE * 2;
            #pragma unroll
            for (int mi = 0; mi < 3; mi++) {
                const uint32_t mb = sbase + stoff + (uint32_t)mi * TILEE * 2;
                cp16(mb + so_b,  mat[mi] + (size_t)lrow * K + k0 + lseg);
                cp16(mb + so_b2, mat[mi] + (size_t)(lrow + 64) * K + k0 + lseg);
            }
            asm volatile("cp.async.commit_group;\n");
            asm volatile("cp.async.wait_group 1;\n");
        } else {
            asm volatile("cp.async.wait_group 0;\n");
        }
        __syncthreads();

        const uint32_t stoff = (uint32_t)((c & 1) * 3) * TILEE * 2;
        const uint32_t bAh = sbase + stoff;
        const uint32_t bAl = bAh + TILEE * 2;
        const uint32_t bB  = bAl + TILEE * 2;

        #pragma unroll
        for (int s = 0; s < 2; s++) {
            const uint32_t ko = s * 32;
            uint32_t ah[4][4], al[4][4], bb[2][4];
            #pragma unroll
            for (int mf = 0; mf < 4; mf++) {
                ldm4(ah[mf], bAh + a_lane + mf * 1280 + ko);
                ldm4(al[mf], bAl + a_lane + mf * 1280 + ko);
            }
            #pragma unroll
            for (int np = 0; np < 2; np++)
                ldm4(bb[np], bB + b_lane + np * 1280 + ko);
            #pragma unroll
            for (int mf = 0; mf < 4; mf++) {
                #pragma unroll
                for (int nf = 0; nf < 4; nf++) {
                    const int np = nf >> 1, h = (nf & 1) * 2;
                    mma16816h(acc[mf][nf], ah[mf], bb[np][h], bb[np][h + 1]);
                    mma16816h(acc[mf][nf], al[mf], bb[np][h], bb[np][h + 1]);
                }
            }
        }
        __syncthreads();
    }

    const int crow0 = m0 + wm * 64 + (lane >> 2);
    const int ccol0 = n0 + wn * 32 + (lane & 3) * 2;
    #pragma unroll
    for (int mf = 0; mf < 4; mf++) {
        #pragma unroll
        for (int nf = 0; nf < 4; nf++) {
            const int gr = crow0 + mf * 16;
            const int gc = ccol0 + nf * 8;
            float2 v0 = make_float2(acc[mf][nf][0], acc[mf][nf][1]);
            float2 v1 = make_float2(acc[mf][nf][2], acc[mf][nf][3]);
            if (Dres) {
                float2 d0 = *(const float2*)(Dres + (size_t)gr * N_ + gc);
                float2 d1 = *(const float2*)(Dres + (size_t)(gr + 8) * N_ + gc);
                v0.x += d0.x; v0.y += d0.y;
                v1.x += d1.x; v1.y += d1.y;
            }
            *(float2*)(C + (size_t)gr * N_ + gc) = v0;
            *(float2*)(C + (size_t)(gr + 8) * N_ + gc) = v1;
        }
    }
}

// ---------------- AC / BD batched GEMM (K=64, fp32 FFMA), merged launch -----
__global__ void __launch_bounds__(256) acbd_kernel(
    const float* __restrict__ wheads, const float* __restrict__ rk,
    const float* __restrict__ rwb, const float* __restrict__ rrb,
    float* __restrict__ ACo, float* __restrict__ BDo)
{
    __shared__ float As[16][132];
    __shared__ float Bs[16][132];
    const int z = blockIdx.z;
    const int mode = z >> 3, bg = z & 7;
    const int b = bg >> 1, g = bg & 1;
    const int bx = blockIdx.x, by = blockIdx.y;
    const int t  = threadIdx.x;
    const int tx = t & 15, ty = t >> 4;

    const float* Aoff = wheads + b * QKVOUT + g * 64;
    const float* Boff = mode ? (rk + g * 64)
                             : (wheads + b * QKVOUT + QKD + g * 64);
    const int lda = BSZ * QKVOUT;
    const int ldb = mode ? QKD : (BSZ * QKVOUT);
    const float* bb = (mode ? rrb : rwb) + g * 64;

    float acc[8][8];
    #pragma unroll
    for (int i = 0; i < 8; i++)
        #pragma unroll
        for (int j = 0; j < 8; j++) acc[i][j] = 0.f;

    const int lrow = t >> 2;
    const int lk4  = (t & 3) * 4;

    for (int k0 = 0; k0 < 64; k0 += 16) {
        float4 bias4 = *(const float4*)(bb + k0 + lk4);
        #pragma unroll
        for (int rr = 0; rr < 2; rr++) {
            int m = lrow + rr * 64;
            int gm = by * 128 + m;
            float4 a = *(const float4*)(Aoff + (size_t)gm * lda + k0 + lk4);
            As[lk4 + 0][m] = a.x + bias4.x; As[lk4 + 1][m] = a.y + bias4.y;
            As[lk4 + 2][m] = a.z + bias4.z; As[lk4 + 3][m] = a.w + bias4.w;
            int gn = bx * 128 + m;
            float4 bv = *(const float4*)(Boff + (size_t)gn * ldb + k0 + lk4);
            Bs[lk4 + 0][m] = bv.x; Bs[lk4 + 1][m] = bv.y;
            Bs[lk4 + 2][m] = bv.z; Bs[lk4 + 3][m] = bv.w;
        }
        __syncthreads();
        #pragma unroll
        for (int kk = 0; kk < 16; kk++) {
            float ar[8], br[8];
            #pragma unroll
            for (int u = 0; u < 8; u++) ar[u] = As[kk][ty * 8 + u];
            #pragma unroll
            for (int u = 0; u < 8; u++) br[u] = Bs[kk][tx * 8 + u];
            #pragma unroll
            for (int i = 0; i < 8; i++)
                #pragma unroll
                for (int j = 0; j < 8; j++) acc[i][j] += ar[i] * br[j];
        }
        __syncthreads();
    }
    float* C = (mode ? BDo : ACo) + (size_t)bg * QLEN * QLEN;
    const int mbase = by * 128 + ty * 8;
    const int nbase = bx * 128 + tx * 8;
    #pragma unroll
    for (int i = 0; i < 8; i++) {
        size_t roff = (size_t)(mbase + i) * QLEN + nbase;
        #pragma unroll
        for (int j0 = 0; j0 < 8; j0 += 4) {
            float4 o;
            o.x = acc[i][j0 + 0]; o.y = acc[i][j0 + 1];
            o.z = acc[i][j0 + 2]; o.w = acc[i][j0 + 3];
            *(float4*)(C + roff + j0) = o;
        }
    }
}

// ---------------- score + rel_shift + mask + softmax -> fp16 P --------------
#define SC_SMEM (16 * 1024 * 4)

__global__ void __launch_bounds__(256) score_kernel(
    const float* __restrict__ AC, const float* __restrict__ BD,
    const float* __restrict__ masks, const float* __restrict__ mproj,
    __half* __restrict__ P)
{
    extern __shared__ float S[];              // [16][1024]
    const int i = blockIdx.x, b = blockIdx.y;
    const int t = threadIdx.x;
    const int warp = t >> 5, lane = t & 31;

    float mp0[16], mp1[16], mp2[16];
    #pragma unroll
    for (int h = 0; h < 16; h++) {
        mp0[h] = mproj[h];
        mp1[h] = mproj[16 + h];
        mp2[h] = mproj[32 + h];
    }

    const float* ac0r = AC + ((size_t)(b * 2 + 0) * QLEN + i) * QLEN;
    const float* ac1r = AC + ((size_t)(b * 2 + 1) * QLEN + i) * QLEN;
    const float* bd0b = BD + (size_t)(b * 2 + 0) * QLEN * QLEN;
    const float* bd1b = BD + (size_t)(b * 2 + 1) * QLEN * QLEN;

    #pragma unroll
    for (int k = 0; k < 4; k++) {
        const int j = t + k * 256;
        float ac0 = ac0r[j], ac1 = ac1r[j];
        unsigned s  = (unsigned)(i + 1) * 1024u + (unsigned)j;
        unsigned i2 = s / 1025u;
        unsigned j2 = s - i2 * 1025u;
        float bd0 = 0.f, bd1 = 0.f;
        if (j2) {
            bd0 = bd0b[(size_t)i2 * QLEN + (j2 - 1u)];
            bd1 = bd1b[(size_t)i2 * QLEN + (j2 - 1u)];
        }
        const float* mr = masks + ((size_t)i * QLEN + j) * 3;
        float m0 = mr[0], m1 = mr[1], m2 = mr[2];
        float base0 = (ac0 + bd0) * SCALE;
        float base1 = (ac1 + bd1) * SCALE;
        #pragma unroll
        for (int h = 0; h < 8; h++) {
            float mw = m0 * mp0[h] + m1 * mp1[h] + m2 * mp2[h];
            S[h * 1024 + j] = base0 * mw;
        }
        #pragma unroll
        for (int h = 8; h < 16; h++) {
            float mw = m0 * mp0[h] + m1 * mp1[h] + m2 * mp2[h];
            S[h * 1024 + j] = base1 * mw;
        }
    }
    __syncthreads();

    #pragma unroll
    for (int hh = 0; hh < 2; hh++) {
        const int h = warp * 2 + hh;
        float* Sh = S + h * 1024;
        float mx = -1e30f;
        #pragma unroll 8
        for (int j = lane; j < 1024; j += 32) mx = fmaxf(mx, Sh[j]);
        #pragma unroll
        for (int o = 16; o > 0; o >>= 1)
            mx = fmaxf(mx, __shfl_xor_sync(0xffffffffu, mx, o));
        float sum = 0.f;
        #pragma unroll 8
        for (int j = lane; j < 1024; j += 32) {
            float e = __expf(Sh[j] - mx);
            Sh[j] = e;
            sum += e;
        }
        #pragma unroll
        for (int o = 16; o > 0; o >>= 1)
            sum += __shfl_xor_sync(0xffffffffu, sum, o);
        const float inv = 1.f / sum;
        __half* ph = P + ((size_t)(b * 16 + h) * QLEN + i) * QLEN;
        #pragma unroll 8
        for (int j = lane; j < 1024; j += 32)
            ph[j] = __float2half_rn(Sh[j] * inv);
    }
}

// ---------------- V transpose-convert: wheads -> Vt[b][h][d][j] fp16 --------
__global__ void __launch_bounds__(256) cvt_vt(
    const float* __restrict__ wheads,
    __half* __restrict__ Vthi, __half* __restrict__ Vtlo)
{
    __shared__ float sm[64 * 33];
    const int bh = blockIdx.y;
    const int b = bh >> 4, h = bh & 15;
    const int j0 = blockIdx.x * 32;
    const int t = threadIdx.x;

    #pragma unroll
    for (int k = 0; k < 8; k++) {
        int idx = t + k * 256;
        int j = idx >> 6, d = idx & 63;
        sm[d * 33 + j] = wheads[(size_t)(j0 + j) * (BSZ * QKVOUT) +
                                b * QKVOUT + 2 * QKD + h * 64 + d];
    }
    __syncthreads();
    #pragma unroll
    for (int k = 0; k < 8; k++) {
        int idx = t + k * 256;
        int d = idx >> 5, j = idx & 31;
        float v = sm[d * 33 + j];
        __half hi = __float2half_rn(v);
        size_t o = ((size_t)(bh * 64 + d)) * QLEN + j0 + j;
        Vthi[o] = hi;
        Vtlo[o] = __float2half_rn(v - __half2float(hi));
    }
}

// ---------------- PV GEMM: avec[i,d] = sum_j P[i,j] * Vt[d,j] ---------------
#define PV_TILEA (128 * LDSB)
#define PV_TILEB (64 * LDSB)
#define PV_STAGE (PV_TILEA + 2 * PV_TILEB)
#define PV_SMEM  (2 * PV_STAGE * 2)

__global__ void __launch_bounds__(256) pv_gemm(
    const __half* __restrict__ P,
    const __half* __restrict__ Vthi, const __half* __restrict__ Vtlo,
    float* __restrict__ avec)
{
    extern __shared__ __half psm[];
    const uint32_t sbase = smem_u32(psm);
    const int bh = blockIdx.y;
    const int b = bh >> 4, h = bh & 15;
    const int i0 = blockIdx.x * 128;
    const int t = threadIdx.x;
    const int warp = t >> 5, lane = t & 31;
    const int wm = warp >> 1, wn = warp & 1;

    float acc[2][4][4];
    #pragma unroll
    for (int i = 0; i < 2; i++)
        #pragma unroll
        for (int j = 0; j < 4; j++)
            #pragma unroll
            for (int u = 0; u < 4; u++) acc[i][j][u] = 0.f;

    const __half* pA = P + ((size_t)bh * QLEN + i0) * QLEN;
    const __half* pB[2];
    pB[0] = Vthi + (size_t)bh * 64 * QLEN;
    pB[1] = Vtlo + (size_t)bh * 64 * QLEN;

    const int arow = t >> 1;
    const int aoff = (t & 1) * 16;
    const int vrow = (t & 127) >> 1;
    const int voff = (t & 1) * 16;

    const uint32_t a_lane =
        ((uint32_t)(wm * 32 + (lane & 15)) * LDSB + (lane >> 4) * 8) * 2;
    const uint32_t b_lane =
        ((uint32_t)(wn * 32 + (lane & 7) + (lane >> 4) * 8) * LDSB +
         ((lane >> 3) & 1) * 8) * 2;

    // prologue stage 0
    {
        const uint32_t so = ((uint32_t)arow * LDSB + aoff) * 2;
        cp16(sbase + so,      pA + (size_t)arow * QLEN + aoff);
        cp16(sbase + so + 16, pA + (size_t)arow * QLEN + aoff + 8);
        if (t < 128) {
            #pragma unroll
            for (int m = 0; m < 2; m++) {
                const uint32_t mb = sbase +
                    (uint32_t)(PV_TILEA + m * PV_TILEB) * 2;
                const uint32_t sv = ((uint32_t)vrow * LDSB + voff) * 2;
                cp16(mb + sv,      pB[m] + (size_t)vrow * QLEN + voff);
                cp16(mb + sv + 16, pB[m] + (size_t)vrow * QLEN + voff + 8);
            }
        }
        asm volatile("cp.async.commit_group;\n");
    }

    const int NCH = QLEN >> 5;
    for (int c = 0; c < NCH; c++) {
        if (c + 1 < NCH) {
            const int k0 = (c + 1) << 5;
            const uint32_t stoff = (uint32_t)(((c + 1) & 1) * PV_STAGE) * 2;
            const uint32_t so = ((uint32_t)arow * LDSB + aoff) * 2;
            cp16(sbase + stoff + so,      pA + (size_t)arow * QLEN + k0 + aoff);
            cp16(sbase + stoff + so + 16, pA + (size_t)arow * QLEN + k0 + aoff + 8);
            if (t < 128) {
                #pragma unroll
                for (int m = 0; m < 2; m++) {
                    const uint32_t mb = sbase + stoff +
                        (uint32_t)(PV_TILEA + m * PV_TILEB) * 2;
                    const uint32_t sv = ((uint32_t)vrow * LDSB + voff) * 2;
                    cp16(mb + sv,      pB[m] + (size_t)vrow * QLEN + k0 + voff);
                    cp16(mb + sv + 16, pB[m] + (size_t)vrow * QLEN + k0 + voff + 8);
                }
            }
            asm volatile("cp.async.commit_group;\n");
            asm volatile("cp.async.wait_group 1;\n");
        } else {
            asm volatile("cp.async.wait_group 0;\n");
        }
        __syncthreads();

        const uint32_t stoff = (uint32_t)((c & 1) * PV_STAGE) * 2;
        const uint32_t bP  = sbase + stoff;
        const uint32_t bVh = bP + (uint32_t)PV_TILEA * 2;
        const uint32_t bVl = bVh + (uint32_t)PV_TILEB * 2;

        #pragma unroll
        for (int s = 0; s < 2; s++) {
            const uint32_t ko = s * 32;
            uint32_t ap[2][4], vh[2][4], vl[2][4];
            #pragma unroll
            for (int mf = 0; mf < 2; mf++)
                ldm4(ap[mf], bP + a_lane + mf * 1280 + ko);
            #pragma unroll
            for (int np = 0; np < 2; np++) {
                ldm4(vh[np], bVh + b_lane + np * 1280 + ko);
                ldm4(vl[np], bVl + b_lane + np * 1280 + ko);
            }
            #pragma unroll
            for (int mf = 0; mf < 2; mf++) {
                #pragma unroll
                for (int nf = 0; nf < 4; nf++) {
                    const int np = nf >> 1, hb = (nf & 1) * 2;
                    mma16816h(acc[mf][nf], ap[mf], vh[np][hb], vh[np][hb + 1]);
                    mma16816h(acc[mf][nf], ap[mf], vl[np][hb], vl[np][hb + 1]);
                }
            }
        }
        __syncthreads();
    }

    const int rloc0 = wm * 32 + (lane >> 2);
    const int col0  = wn * 32 + (lane & 3) * 2;
    #pragma unroll
    for (int mf = 0; mf < 2; mf++) {
        #pragma unroll
        for (int nf = 0; nf < 4; nf++) {
            const int gr0 = i0 + rloc0 + mf * 16;
            const int gc  = col0 + nf * 8;
            float* o0 = avec + ((size_t)(gr0 * BSZ + b) * NHEAD + h) * 64 + gc;
            float* o1 = avec + ((size_t)((gr0 + 8) * BSZ + b) * NHEAD + h) * 64 + gc;
            *(float2*)o0 = make_float2(acc[mf][nf][0], acc[mf][nf][1]);
            *(float2*)o1 = make_float2(acc[mf][nf][2], acc[mf][nf][3]);
        }
    }
}

// ---------------- LayerNorm --------------------------------------------------
__global__ void __launch_bounds__(256) ln_kernel(
    const float* __restrict__ X, const float* __restrict__ gamma,
    const float* __restrict__ beta, float* __restrict__ out)
{
    const int row = blockIdx.x;
    const int t = threadIdx.x;
    const float4* x4 = (const float4*)(X + (size_t)row * DMODEL);
    float4 v = x4[t];
    float s  = v.x + v.y + v.z + v.w;
    float sq = v.x * v.x + v.y * v.y + v.z * v.z + v.w * v.w;
    #pragma unroll
    for (int o = 16; o > 0; o >>= 1) {
        s  += __shfl_xor_sync(0xffffffffu, s,  o);
        sq += __shfl_xor_sync(0xffffffffu, sq, o);
    }
    __shared__ float ssum[8], ssq[8];
    __shared__ float smu, srstd;
    if ((t & 31) == 0) { ssum[t >> 5] = s; ssq[t >> 5] = sq; }
    __syncthreads();
    if (t == 0) {
        float ts = 0.f, tq = 0.f;
        #pragma unroll
        for (int k = 0; k < 8; k++) { ts += ssum[k]; tq += ssq[k]; }
        float mu = ts * (1.f / DMODEL);
        float var = tq * (1.f / DMODEL) - mu * mu;
        smu = mu;
        srstd = rsqrtf(var + LN_EPS);
    }
    __syncthreads();
    float mu = smu, rstd = srstd;
    float4 gm = ((const float4*)gamma)[t];
    float4 bt = ((const float4*)beta)[t];
    float4 o;
    o.x = (v.x - mu) * rstd * gm.x + bt.x;
    o.y = (v.y - mu) * rstd * gm.y + bt.y;
    o.z = (v.z - mu) * rstd * gm.z + bt.z;
    o.w = (v.w - mu) * rstd * gm.w + bt.w;
    ((float4*)(out + (size_t)row * DMODEL))[t] = o;
}

// ---------------- launch ----------------------------------------------------
extern "C" void kernel_launch(void* const* d_in, const int* in_sizes, int n_in,
                              void* d_out, int out_size)
{
    const float* w     = (const float*)d_in[0];
    const float* r     = (const float*)d_in[1];
    const float* rwb   = (const float*)d_in[2];
    const float* rrb   = (const float*)d_in[3];
    const float* masks = (const float*)d_in[4];
    const float* Wqkv  = (const float*)d_in[5];
    const float* Wr    = (const float*)d_in[6];
    const float* mproj = (const float*)d_in[7];
    const float* Wo    = (const float*)d_in[8];
    const float* gamma = (const float*)d_in[9];
    const float* beta  = (const float*)d_in[10];
    float* out = (float*)d_out;

    float *wheads, *rkp, *acp, *bdp, *avp, *xp;
    cudaGetSymbolAddress((void**)&wheads, g_wheads);
    cudaGetSymbolAddress((void**)&rkp,    g_rk);
    cudaGetSymbolAddress((void**)&acp,    g_AC);
    cudaGetSymbolAddress((void**)&bdp,    g_BD);
    cudaGetSymbolAddress((void**)&avp,    g_avec);
    cudaGetSymbolAddress((void**)&xp,     g_x);

    __half *Ah, *Al, *Bp, *Pp, *Vth, *Vtl;
    cudaGetSymbolAddress((void**)&Ah,  g_hA_hi);
    cudaGetSymbolAddress((void**)&Al,  g_hA_lo);
    cudaGetSymbolAddress((void**)&Bp,  g_hB);
    cudaGetSymbolAddress((void**)&Pp,  g_P);
    cudaGetSymbolAddress((void**)&Vth, g_Vthi);
    cudaGetSymbolAddress((void**)&Vtl, g_Vtlo);

    cudaFuncSetAttribute(mma_gemm,
                         cudaFuncAttributeMaxDynamicSharedMemorySize, GEMM_SMEM);
    cudaFuncSetAttribute(score_kernel,
                         cudaFuncAttributeMaxDynamicSharedMemorySize, SC_SMEM);
    cudaFuncSetAttribute(pv_gemm,
                         cudaFuncAttributeMaxDynamicSharedMemorySize, PV_SMEM);

    // 1) w_heads = w @ W_qkv^T
    cvt_split_h<<<(MROWS * DMODEL) / 1024, 256>>>(w, Ah, Al, MROWS * DMODEL);
    cvt_h<<<(QKVOUT * DMODEL) / 1024, 256>>>(Wqkv, Bp, QKVOUT * DMODEL);
    mma_gemm<<<dim3(QKVOUT / 128, MROWS / 128), 256, GEMM_SMEM>>>(
        Ah, Al, Bp, nullptr, wheads, QKVOUT, DMODEL);

    // 2) r_head_k = r @ W_r^T
    cvt_split_h<<<(QLEN * DMODEL) / 1024, 256>>>(r, Ah, Al, QLEN * DMODEL);
    cvt_h<<<(QKD * DMODEL) / 1024, 256>>>(Wr, Bp, QKD * DMODEL);
    mma_gemm<<<dim3(QKD / 128, QLEN / 128), 256, GEMM_SMEM>>>(
        Ah, Al, Bp, nullptr, rkp, QKD, DMODEL);

    // 3) AC, BD (FFMA, merged single launch)
    acbd_kernel<<<dim3(8, 8, 16), 256>>>(wheads, rkp, rwb, rrb, acp, bdp);

    // 4a) scores + softmax -> fp16 P
    score_kernel<<<dim3(QLEN, BSZ), 256, SC_SMEM>>>(
        acp, bdp, masks, mproj, Pp);

    // 4b) V transpose-convert (fp16 hi/lo)
    cvt_vt<<<dim3(QLEN / 32, BSZ * NHEAD), 256>>>(wheads, Vth, Vtl);

    // 4c) PV GEMM -> avec
    pv_gemm<<<dim3(QLEN / 128, BSZ * NHEAD), 256, PV_SMEM>>>(
        Pp, Vth, Vtl, avp);

    // 5) x = attn_vec @ W_o^T + w
    cvt_split_h<<<(MROWS * DMODEL) / 1024, 256>>>(avp, Ah, Al, MROWS * DMODEL);
    cvt_h<<<(DMODEL * DMODEL) / 1024, 256>>>(Wo, Bp, DMODEL * DMODEL);
    mma_gemm<<<dim3(DMODEL / 128, MROWS / 128), 256, GEMM_SMEM>>>(
        Ah, Al, Bp, w, xp, DMODEL, DMODEL);

    // 6) LayerNorm -> out
    ln_kernel<<<MROWS, 256>>>(xp, gamma, beta, out);
}

// round 15
// speedup vs baseline: 2.3750x; 1.1729x over previous
#include <cuda_runtime.h>
#include <cuda_bf16.h>
#include <cuda_fp16.h>
#include <math.h>
#include <stdint.h>

#define QLEN   1024
#define BSZ    4
#define DMODEL 1024
#define NHEAD  16
#define GHEADS 2
#define DHEAD  64
#define QKD    128
#define QKVOUT 1280
#define MROWS  4096
#define SCALE  0.125f
#define LN_EPS 1e-5f

// ---------------- scratch (device globals; no allocations allowed) ----------
__device__ float g_wheads[MROWS * QKVOUT];
__device__ float g_rk[QLEN * QKD];
__device__ float g_AC[BSZ * GHEADS * QLEN * QLEN];
__device__ float g_BD[BSZ * GHEADS * QLEN * QLEN];
__device__ float g_avec[MROWS * DMODEL];
__device__ float g_x[MROWS * DMODEL];

// fp16 GEMM operands (single-term A and B)
__device__ __half g_hA[MROWS * DMODEL];
__device__ __half g_hB[QKVOUT * DMODEL];

// normalized probabilities, single fp16: [b][h][i][j]  (134 MB)
__device__ __half g_P[BSZ * NHEAD * QLEN * QLEN];
// V transposed [b][h][d][j], fp16 hi/lo
__device__ __half g_Vthi[BSZ * NHEAD * DHEAD * QLEN];
__device__ __half g_Vtlo[BSZ * NHEAD * DHEAD * QLEN];

// ---------------- helpers ----------------------------------------------------
__device__ __forceinline__ uint32_t smem_u32(const void* p) {
    uint32_t a;
    asm("{ .reg .u64 t; cvta.to.shared.u64 t, %1; cvt.u32.u64 %0, t; }"
        : "=r"(a) : "l"(p));
    return a;
}
__device__ __forceinline__ void ldm4(uint32_t* r, uint32_t addr) {
    asm volatile("ldmatrix.sync.aligned.m8n8.x4.shared.b16 {%0,%1,%2,%3}, [%4];"
                 : "=r"(r[0]), "=r"(r[1]), "=r"(r[2]), "=r"(r[3]) : "r"(addr));
}
__device__ __forceinline__ void mma16816h(float* c, const uint32_t* a,
                                          uint32_t b0, uint32_t b1) {
    asm volatile(
        "mma.sync.aligned.m16n8k16.row.col.f32.f16.f16.f32 "
        "{%0,%1,%2,%3}, {%4,%5,%6,%7}, {%8,%9}, {%0,%1,%2,%3};"
        : "+f"(c[0]), "+f"(c[1]), "+f"(c[2]), "+f"(c[3])
        : "r"(a[0]), "r"(a[1]), "r"(a[2]), "r"(a[3]), "r"(b0), "r"(b1));
}
__device__ __forceinline__ void cp16(uint32_t saddr, const void* gaddr) {
    asm volatile("cp.async.cg.shared.global [%0], [%1], 16;\n"
                 :: "r"(saddr), "l"(gaddr) : "memory");
}

// ---------------- fp32 -> fp16 hi/lo split (used for V only) ----------------
__global__ void __launch_bounds__(256) cvt_split_h(
    const float* __restrict__ x, __half* __restrict__ hi,
    __half* __restrict__ lo, int n)
{
    int i = (blockIdx.x * 256 + threadIdx.x) * 4;
    if (i >= n) return;
    float4 v = *(const float4*)(x + i);
    union { __half b[4]; uint2 u; } H, L;
    H.b[0] = __float2half_rn(v.x);
    H.b[1] = __float2half_rn(v.y);
    H.b[2] = __float2half_rn(v.z);
    H.b[3] = __float2half_rn(v.w);
    L.b[0] = __float2half_rn(v.x - __half2float(H.b[0]));
    L.b[1] = __float2half_rn(v.y - __half2float(H.b[1]));
    L.b[2] = __float2half_rn(v.z - __half2float(H.b[2]));
    L.b[3] = __float2half_rn(v.w - __half2float(H.b[3]));
    *(uint2*)(hi + i) = H.u;
    *(uint2*)(lo + i) = L.u;
}

// ---------------- fp32 -> fp16 single ----------------------------------------
__global__ void __launch_bounds__(256) cvt_h(
    const float* __restrict__ x, __half* __restrict__ o, int n)
{
    int i = (blockIdx.x * 256 + threadIdx.x) * 4;
    if (i >= n) return;
    float4 v = *(const float4*)(x + i);
    union { __half b[4]; uint2 u; } H;
    H.b[0] = __float2half_rn(v.x);
    H.b[1] = __float2half_rn(v.y);
    H.b[2] = __float2half_rn(v.z);
    H.b[3] = __float2half_rn(v.w);
    *(uint2*)(o + i) = H.u;
}

// ---------------- fp16 1-term NT GEMM, cp.async double-buffered -------------
// C[m,n] = sum_k A[m,k]*B[n,k] (+Dres), A and B single fp16.
// BM=BN=128, BK=32. 256 threads = 8 warps (2m x 4n), warp tile 64x32.
#define LDSB  40
#define TILEE (128 * LDSB)
#define GEMM_SMEM (2 * 2 * TILEE * 2)      // 40960 bytes

__global__ void __launch_bounds__(256) mma_gemm(
    const __half* __restrict__ A, const __half* __restrict__ B,
    const float* __restrict__ Dres, float* __restrict__ C, int N_, int K)
{
    extern __shared__ __half gsm[];
    const uint32_t sbase = smem_u32(gsm);

    const int t = threadIdx.x;
    const int warp = t >> 5, lane = t & 31;
    const int wm = warp >> 2, wn = warp & 3;
    const int m0 = blockIdx.y * 128, n0 = blockIdx.x * 128;

    float acc[4][4][4];
    #pragma unroll
    for (int i = 0; i < 4; i++)
        #pragma unroll
        for (int j = 0; j < 4; j++)
            #pragma unroll
            for (int u = 0; u < 4; u++) acc[i][j][u] = 0.f;

    const int lrow = t >> 2;
    const int lseg = (t & 3) * 8;

    const __half* mat[2];
    mat[0] = A + (size_t)m0 * K;
    mat[1] = B + (size_t)n0 * K;

    const uint32_t so_b = ((uint32_t)lrow * LDSB + lseg) * 2;
    const uint32_t so_b2 = so_b + (uint32_t)64 * LDSB * 2;

    const uint32_t a_lane =
        ((uint32_t)(wm * 64 + (lane & 15)) * LDSB + (lane >> 4) * 8) * 2;
    const uint32_t b_lane =
        ((uint32_t)(wn * 32 + (lane & 7) + (lane >> 4) * 8) * LDSB +
         ((lane >> 3) & 1) * 8) * 2;

    const int NCH = K >> 5;

    #pragma unroll
    for (int mi = 0; mi < 2; mi++) {
        const uint32_t mb = sbase + (uint32_t)mi * TILEE * 2;
        cp16(mb + so_b,  mat[mi] + (size_t)lrow * K + lseg);
        cp16(mb + so_b2, mat[mi] + (size_t)(lrow + 64) * K + lseg);
    }
    asm volatile("cp.async.commit_group;\n");

    for (int c = 0; c < NCH; c++) {
        if (c + 1 < NCH) {
            const int k0 = (c + 1) << 5;
            const uint32_t stoff = (uint32_t)(((c + 1) & 1) * 2) * TILEE * 2;
            #pragma unroll
            for (int mi = 0; mi < 2; mi++) {
                const uint32_t mb = sbase + stoff + (uint32_t)mi * TILEE * 2;
                cp16(mb + so_b,  mat[mi] + (size_t)lrow * K + k0 + lseg);
                cp16(mb + so_b2, mat[mi] + (size_t)(lrow + 64) * K + k0 + lseg);
            }
            asm volatile("cp.async.commit_group;\n");
            asm volatile("cp.async.wait_group 1;\n");
        } else {
            asm volatile("cp.async.wait_group 0;\n");
        }
        __syncthreads();

        const uint32_t stoff = (uint32_t)((c & 1) * 2) * TILEE * 2;
        const uint32_t bA = sbase + stoff;
        const uint32_t bB = bA + TILEE * 2;

        #pragma unroll
        for (int s = 0; s < 2; s++) {
            const uint32_t ko = s * 32;
            uint32_t ah[4][4], bb[2][4];
            #pragma unroll
            for (int mf = 0; mf < 4; mf++)
                ldm4(ah[mf], bA + a_lane + mf * 1280 + ko);
            #pragma unroll
            for (int np = 0; np < 2; np++)
                ldm4(bb[np], bB + b_lane + np * 1280 + ko);
            #pragma unroll
            for (int mf = 0; mf < 4; mf++) {
                #pragma unroll
                for (int nf = 0; nf < 4; nf++) {
                    const int np = nf >> 1, h = (nf & 1) * 2;
                    mma16816h(acc[mf][nf], ah[mf], bb[np][h], bb[np][h + 1]);
                }
            }
        }
        __syncthreads();
    }

    const int crow0 = m0 + wm * 64 + (lane >> 2);
    const int ccol0 = n0 + wn * 32 + (lane & 3) * 2;
    #pragma unroll
    for (int mf = 0; mf < 4; mf++) {
        #pragma unroll
        for (int nf = 0; nf < 4; nf++) {
            const int gr = crow0 + mf * 16;
            const int gc = ccol0 + nf * 8;
            float2 v0 = make_float2(acc[mf][nf][0], acc[mf][nf][1]);
            float2 v1 = make_float2(acc[mf][nf][2], acc[mf][nf][3]);
            if (Dres) {
                float2 d0 = *(const float2*)(Dres + (size_t)gr * N_ + gc);
                float2 d1 = *(const float2*)(Dres + (size_t)(gr + 8) * N_ + gc);
                v0.x += d0.x; v0.y += d0.y;
                v1.x += d1.x; v1.y += d1.y;
            }
            *(float2*)(C + (size_t)gr * N_ + gc) = v0;
            *(float2*)(C + (size_t)(gr + 8) * N_ + gc) = v1;
        }
    }
}

// ---------------- AC / BD batched GEMM (K=64, fp32 FFMA), merged launch -----
__global__ void __launch_bounds__(256) acbd_kernel(
    const float* __restrict__ wheads, const float* __restrict__ rk,
    const float* __restrict__ rwb, const float* __restrict__ rrb,
    float* __restrict__ ACo, float* __restrict__ BDo)
{
    __shared__ float As[16][132];
    __shared__ float Bs[16][132];
    const int z = blockIdx.z;
    const int mode = z >> 3, bg = z & 7;
    const int b = bg >> 1, g = bg & 1;
    const int bx = blockIdx.x, by = blockIdx.y;
    const int t  = threadIdx.x;
    const int tx = t & 15, ty = t >> 4;

    const float* Aoff = wheads + b * QKVOUT + g * 64;
    const float* Boff = mode ? (rk + g * 64)
                             : (wheads + b * QKVOUT + QKD + g * 64);
    const int lda = BSZ * QKVOUT;
    const int ldb = mode ? QKD : (BSZ * QKVOUT);
    const float* bb = (mode ? rrb : rwb) + g * 64;

    float acc[8][8];
    #pragma unroll
    for (int i = 0; i < 8; i++)
        #pragma unroll
        for (int j = 0; j < 8; j++) acc[i][j] = 0.f;

    const int lrow = t >> 2;
    const int lk4  = (t & 3) * 4;

    for (int k0 = 0; k0 < 64; k0 += 16) {
        float4 bias4 = *(const float4*)(bb + k0 + lk4);
        #pragma unroll
        for (int rr = 0; rr < 2; rr++) {
            int m = lrow + rr * 64;
            int gm = by * 128 + m;
            float4 a = *(const float4*)(Aoff + (size_t)gm * lda + k0 + lk4);
            As[lk4 + 0][m] = a.x + bias4.x; As[lk4 + 1][m] = a.y + bias4.y;
            As[lk4 + 2][m] = a.z + bias4.z; As[lk4 + 3][m] = a.w + bias4.w;
            int gn = bx * 128 + m;
            float4 bv = *(const float4*)(Boff + (size_t)gn * ldb + k0 + lk4);
            Bs[lk4 + 0][m] = bv.x; Bs[lk4 + 1][m] = bv.y;
            Bs[lk4 + 2][m] = bv.z; Bs[lk4 + 3][m] = bv.w;
        }
        __syncthreads();
        #pragma unroll
        for (int kk = 0; kk < 16; kk++) {
            float ar[8], br[8];
            #pragma unroll
            for (int u = 0; u < 8; u++) ar[u] = As[kk][ty * 8 + u];
            #pragma unroll
            for (int u = 0; u < 8; u++) br[u] = Bs[kk][tx * 8 + u];
            #pragma unroll
            for (int i = 0; i < 8; i++)
                #pragma unroll
                for (int j = 0; j < 8; j++) acc[i][j] += ar[i] * br[j];
        }
        __syncthreads();
    }
    float* C = (mode ? BDo : ACo) + (size_t)bg * QLEN * QLEN;
    const int mbase = by * 128 + ty * 8;
    const int nbase = bx * 128 + tx * 8;
    #pragma unroll
    for (int i = 0; i < 8; i++) {
        size_t roff = (size_t)(mbase + i) * QLEN + nbase;
        #pragma unroll
        for (int j0 = 0; j0 < 8; j0 += 4) {
            float4 o;
            o.x = acc[i][j0 + 0]; o.y = acc[i][j0 + 1];
            o.z = acc[i][j0 + 2]; o.w = acc[i][j0 + 3];
            *(float4*)(C + roff + j0) = o;
        }
    }
}

// ---------------- score + rel_shift + mask + softmax -> fp16 P --------------
#define SC_SMEM (16 * 1024 * 4)

__global__ void __launch_bounds__(256) score_kernel(
    const float* __restrict__ AC, const float* __restrict__ BD,
    const float* __restrict__ masks, const float* __restrict__ mproj,
    __half* __restrict__ P)
{
    extern __shared__ float S[];              // [16][1024]
    const int i = blockIdx.x, b = blockIdx.y;
    const int t = threadIdx.x;
    const int warp = t >> 5, lane = t & 31;

    float mp0[16], mp1[16], mp2[16];
    #pragma unroll
    for (int h = 0; h < 16; h++) {
        mp0[h] = mproj[h];
        mp1[h] = mproj[16 + h];
        mp2[h] = mproj[32 + h];
    }

    const float* ac0r = AC + ((size_t)(b * 2 + 0) * QLEN + i) * QLEN;
    const float* ac1r = AC + ((size_t)(b * 2 + 1) * QLEN + i) * QLEN;
    const float* bd0b = BD + (size_t)(b * 2 + 0) * QLEN * QLEN;
    const float* bd1b = BD + (size_t)(b * 2 + 1) * QLEN * QLEN;

    #pragma unroll
    for (int k = 0; k < 4; k++) {
        const int j = t + k * 256;
        float ac0 = ac0r[j], ac1 = ac1r[j];
        unsigned s  = (unsigned)(i + 1) * 1024u + (unsigned)j;
        unsigned i2 = s / 1025u;
        unsigned j2 = s - i2 * 1025u;
        float bd0 = 0.f, bd1 = 0.f;
        if (j2) {
            bd0 = bd0b[(size_t)i2 * QLEN + (j2 - 1u)];
            bd1 = bd1b[(size_t)i2 * QLEN + (j2 - 1u)];
        }
        const float* mr = masks + ((size_t)i * QLEN + j) * 3;
        float m0 = mr[0], m1 = mr[1], m2 = mr[2];
        float base0 = (ac0 + bd0) * SCALE;
        float base1 = (ac1 + bd1) * SCALE;
        #pragma unroll
        for (int h = 0; h < 8; h++) {
            float mw = m0 * mp0[h] + m1 * mp1[h] + m2 * mp2[h];
            S[h * 1024 + j] = base0 * mw;
        }
        #pragma unroll
        for (int h = 8; h < 16; h++) {
            float mw = m0 * mp0[h] + m1 * mp1[h] + m2 * mp2[h];
            S[h * 1024 + j] = base1 * mw;
        }
    }
    __syncthreads();

    #pragma unroll
    for (int hh = 0; hh < 2; hh++) {
        const int h = warp * 2 + hh;
        float* Sh = S + h * 1024;
        float mx = -1e30f;
        #pragma unroll 8
        for (int j = lane; j < 1024; j += 32) mx = fmaxf(mx, Sh[j]);
        #pragma unroll
        for (int o = 16; o > 0; o >>= 1)
            mx = fmaxf(mx, __shfl_xor_sync(0xffffffffu, mx, o));
        float sum = 0.f;
        #pragma unroll 8
        for (int j = lane; j < 1024; j += 32) {
            float e = __expf(Sh[j] - mx);
            Sh[j] = e;
            sum += e;
        }
        #pragma unroll
        for (int o = 16; o > 0; o >>= 1)
            sum += __shfl_xor_sync(0xffffffffu, sum, o);
        const float inv = 1.f / sum;
        __half* ph = P + ((size_t)(b * 16 + h) * QLEN + i) * QLEN;
        #pragma unroll 8
        for (int j = lane; j < 1024; j += 32)
            ph[j] = __float2half_rn(Sh[j] * inv);
    }
}

// ---------------- V transpose-convert: wheads -> Vt[b][h][d][j] fp16 --------
__global__ void __launch_bounds__(256) cvt_vt(
    const float* __restrict__ wheads,
    __half* __restrict__ Vthi, __half* __restrict__ Vtlo)
{
    __shared__ float sm[64 * 33];
    const int bh = blockIdx.y;
    const int b = bh >> 4, h = bh & 15;
    const int j0 = blockIdx.x * 32;
    const int t = threadIdx.x;

    #pragma unroll
    for (int k = 0; k < 8; k++) {
        int idx = t + k * 256;
        int j = idx >> 6, d = idx & 63;
        sm[d * 33 + j] = wheads[(size_t)(j0 + j) * (BSZ * QKVOUT) +
                                b * QKVOUT + 2 * QKD + h * 64 + d];
    }
    __syncthreads();
    #pragma unroll
    for (int k = 0; k < 8; k++) {
        int idx = t + k * 256;
        int d = idx >> 5, j = idx & 31;
        float v = sm[d * 33 + j];
        __half hi = __float2half_rn(v);
        size_t o = ((size_t)(bh * 64 + d)) * QLEN + j0 + j;
        Vthi[o] = hi;
        Vtlo[o] = __float2half_rn(v - __half2float(hi));
    }
}

// ---------------- PV GEMM: avec[i,d] = sum_j P[i,j] * Vt[d,j] ---------------
#define PV_TILEA (128 * LDSB)
#define PV_TILEB (64 * LDSB)
#define PV_STAGE (PV_TILEA + 2 * PV_TILEB)
#define PV_SMEM  (2 * PV_STAGE * 2)

__global__ void __launch_bounds__(256) pv_gemm(
    const __half* __restrict__ P,
    const __half* __restrict__ Vthi, const __half* __restrict__ Vtlo,
    float* __restrict__ avec)
{
    extern __shared__ __half psm[];
    const uint32_t sbase = smem_u32(psm);
    const int bh = blockIdx.y;
    const int b = bh >> 4, h = bh & 15;
    const int i0 = blockIdx.x * 128;
    const int t = threadIdx.x;
    const int warp = t >> 5, lane = t & 31;
    const int wm = warp >> 1, wn = warp & 1;

    float acc[2][4][4];
    #pragma unroll
    for (int i = 0; i < 2; i++)
        #pragma unroll
        for (int j = 0; j < 4; j++)
            #pragma unroll
            for (int u = 0; u < 4; u++) acc[i][j][u] = 0.f;

    const __half* pA = P + ((size_t)bh * QLEN + i0) * QLEN;
    const __half* pB[2];
    pB[0] = Vthi + (size_t)bh * 64 * QLEN;
    pB[1] = Vtlo + (size_t)bh * 64 * QLEN;

    const int arow = t >> 1;
    const int aoff = (t & 1) * 16;
    const int vrow = (t & 127) >> 1;
    const int voff = (t & 1) * 16;

    const uint32_t a_lane =
        ((uint32_t)(wm * 32 + (lane & 15)) * LDSB + (lane >> 4) * 8) * 2;
    const uint32_t b_lane =
        ((uint32_t)(wn * 32 + (lane & 7) + (lane >> 4) * 8) * LDSB +
         ((lane >> 3) & 1) * 8) * 2;

    // prologue stage 0
    {
        const uint32_t so = ((uint32_t)arow * LDSB + aoff) * 2;
        cp16(sbase + so,      pA + (size_t)arow * QLEN + aoff);
        cp16(sbase + so + 16, pA + (size_t)arow * QLEN + aoff + 8);
        if (t < 128) {
            #pragma unroll
            for (int m = 0; m < 2; m++) {
                const uint32_t mb = sbase +
                    (uint32_t)(PV_TILEA + m * PV_TILEB) * 2;
                const uint32_t sv = ((uint32_t)vrow * LDSB + voff) * 2;
                cp16(mb + sv,      pB[m] + (size_t)vrow * QLEN + voff);
                cp16(mb + sv + 16, pB[m] + (size_t)vrow * QLEN + voff + 8);
            }
        }
        asm volatile("cp.async.commit_group;\n");
    }

    const int NCH = QLEN >> 5;
    for (int c = 0; c < NCH; c++) {
        if (c + 1 < NCH) {
            const int k0 = (c + 1) << 5;
            const uint32_t stoff = (uint32_t)(((c + 1) & 1) * PV_STAGE) * 2;
            const uint32_t so = ((uint32_t)arow * LDSB + aoff) * 2;
            cp16(sbase + stoff + so,      pA + (size_t)arow * QLEN + k0 + aoff);
            cp16(sbase + stoff + so + 16, pA + (size_t)arow * QLEN + k0 + aoff + 8);
            if (t < 128) {
                #pragma unroll
                for (int m = 0; m < 2; m++) {
                    const uint32_t mb = sbase + stoff +
                        (uint32_t)(PV_TILEA + m * PV_TILEB) * 2;
                    const uint32_t sv = ((uint32_t)vrow * LDSB + voff) * 2;
                    cp16(mb + sv,      pB[m] + (size_t)vrow * QLEN + k0 + voff);
                    cp16(mb + sv + 16, pB[m] + (size_t)vrow * QLEN + k0 + voff + 8);
                }
            }
            asm volatile("cp.async.commit_group;\n");
            asm volatile("cp.async.wait_group 1;\n");
        } else {
            asm volatile("cp.async.wait_group 0;\n");
        }
        __syncthreads();

        const uint32_t stoff = (uint32_t)((c & 1) * PV_STAGE) * 2;
        const uint32_t bP  = sbase + stoff;
        const uint32_t bVh = bP + (uint32_t)PV_TILEA * 2;
        const uint32_t bVl = bVh + (uint32_t)PV_TILEB * 2;

        #pragma unroll
        for (int s = 0; s < 2; s++) {
            const uint32_t ko = s * 32;
            uint32_t ap[2][4], vh[2][4], vl[2][4];
            #pragma unroll
            for (int mf = 0; mf < 2; mf++)
                ldm4(ap[mf], bP + a_lane + mf * 1280 + ko);
            #pragma unroll
            for (int np = 0; np < 2; np++) {
                ldm4(vh[np], bVh + b_lane + np * 1280 + ko);
                ldm4(vl[np], bVl + b_lane + np * 1280 + ko);
            }
            #pragma unroll
            for (int mf = 0; mf < 2; mf++) {
                #pragma unroll
                for (int nf = 0; nf < 4; nf++) {
                    const int np = nf >> 1, hb = (nf & 1) * 2;
                    mma16816h(acc[mf][nf], ap[mf], vh[np][hb], vh[np][hb + 1]);
                    mma16816h(acc[mf][nf], ap[mf], vl[np][hb], vl[np][hb + 1]);
                }
            }
        }
        __syncthreads();
    }

    const int rloc0 = wm * 32 + (lane >> 2);
    const int col0  = wn * 32 + (lane & 3) * 2;
    #pragma unroll
    for (int mf = 0; mf < 2; mf++) {
        #pragma unroll
        for (int nf = 0; nf < 4; nf++) {
            const int gr0 = i0 + rloc0 + mf * 16;
            const int gc  = col0 + nf * 8;
            float* o0 = avec + ((size_t)(gr0 * BSZ + b) * NHEAD + h) * 64 + gc;
            float* o1 = avec + ((size_t)((gr0 + 8) * BSZ + b) * NHEAD + h) * 64 + gc;
            *(float2*)o0 = make_float2(acc[mf][nf][0], acc[mf][nf][1]);
            *(float2*)o1 = make_float2(acc[mf][nf][2], acc[mf][nf][3]);
        }
    }
}

// ---------------- LayerNorm --------------------------------------------------
__global__ void __launch_bounds__(256) ln_kernel(
    const float* __restrict__ X, const float* __restrict__ gamma,
    const float* __restrict__ beta, float* __restrict__ out)
{
    const int row = blockIdx.x;
    const int t = threadIdx.x;
    const float4* x4 = (const float4*)(X + (size_t)row * DMODEL);
    float4 v = x4[t];
    float s  = v.x + v.y + v.z + v.w;
    float sq = v.x * v.x + v.y * v.y + v.z * v.z + v.w * v.w;
    #pragma unroll
    for (int o = 16; o > 0; o >>= 1) {
        s  += __shfl_xor_sync(0xffffffffu, s,  o);
        sq += __shfl_xor_sync(0xffffffffu, sq, o);
    }
    __shared__ float ssum[8], ssq[8];
    __shared__ float smu, srstd;
    if ((t & 31) == 0) { ssum[t >> 5] = s; ssq[t >> 5] = sq; }
    __syncthreads();
    if (t == 0) {
        float ts = 0.f, tq = 0.f;
        #pragma unroll
        for (int k = 0; k < 8; k++) { ts += ssum[k]; tq += ssq[k]; }
        float mu = ts * (1.f / DMODEL);
        float var = tq * (1.f / DMODEL) - mu * mu;
        smu = mu;
        srstd = rsqrtf(var + LN_EPS);
    }
    __syncthreads();
    float mu = smu, rstd = srstd;
    float4 gm = ((const float4*)gamma)[t];
    float4 bt = ((const float4*)beta)[t];
    float4 o;
    o.x = (v.x - mu) * rstd * gm.x + bt.x;
    o.y = (v.y - mu) * rstd * gm.y + bt.y;
    o.z = (v.z - mu) * rstd * gm.z + bt.z;
    o.w = (v.w - mu) * rstd * gm.w + bt.w;
    ((float4*)(out + (size_t)row * DMODEL))[t] = o;
}

// ---------------- launch ----------------------------------------------------
extern "C" void kernel_launch(void* const* d_in, const int* in_sizes, int n_in,
                              void* d_out, int out_size)
{
    const float* w     = (const float*)d_in[0];
    const float* r     = (const float*)d_in[1];
    const float* rwb   = (const float*)d_in[2];
    const float* rrb   = (const float*)d_in[3];
    const float* masks = (const float*)d_in[4];
    const float* Wqkv  = (const float*)d_in[5];
    const float* Wr    = (const float*)d_in[6];
    const float* mproj = (const float*)d_in[7];
    const float* Wo    = (const float*)d_in[8];
    const float* gamma = (const float*)d_in[9];
    const float* beta  = (const float*)d_in[10];
    float* out = (float*)d_out;

    float *wheads, *rkp, *acp, *bdp, *avp, *xp;
    cudaGetSymbolAddress((void**)&wheads, g_wheads);
    cudaGetSymbolAddress((void**)&rkp,    g_rk);
    cudaGetSymbolAddress((void**)&acp,    g_AC);
    cudaGetSymbolAddress((void**)&bdp,    g_BD);
    cudaGetSymbolAddress((void**)&avp,    g_avec);
    cudaGetSymbolAddress((void**)&xp,     g_x);

    __half *Ap, *Bp, *Pp, *Vth, *Vtl;
    cudaGetSymbolAddress((void**)&Ap,  g_hA);
    cudaGetSymbolAddress((void**)&Bp,  g_hB);
    cudaGetSymbolAddress((void**)&Pp,  g_P);
    cudaGetSymbolAddress((void**)&Vth, g_Vthi);
    cudaGetSymbolAddress((void**)&Vtl, g_Vtlo);

    cudaFuncSetAttribute(mma_gemm,
                         cudaFuncAttributeMaxDynamicSharedMemorySize, GEMM_SMEM);
    cudaFuncSetAttribute(score_kernel,
                         cudaFuncAttributeMaxDynamicSharedMemorySize, SC_SMEM);
    cudaFuncSetAttribute(pv_gemm,
                         cudaFuncAttributeMaxDynamicSharedMemorySize, PV_SMEM);

    // 1) w_heads = w @ W_qkv^T  (fp16 1-term HMMA)
    cvt_h<<<(MROWS * DMODEL) / 1024, 256>>>(w, Ap, MROWS * DMODEL);
    cvt_h<<<(QKVOUT * DMODEL) / 1024, 256>>>(Wqkv, Bp, QKVOUT * DMODEL);
    mma_gemm<<<dim3(QKVOUT / 128, MROWS / 128), 256, GEMM_SMEM>>>(
        Ap, Bp, nullptr, wheads, QKVOUT, DMODEL);

    // 2) r_head_k = r @ W_r^T
    cvt_h<<<(QLEN * DMODEL) / 1024, 256>>>(r, Ap, QLEN * DMODEL);
    cvt_h<<<(QKD * DMODEL) / 1024, 256>>>(Wr, Bp, QKD * DMODEL);
    mma_gemm<<<dim3(QKD / 128, QLEN / 128), 256, GEMM_SMEM>>>(
        Ap, Bp, nullptr, rkp, QKD, DMODEL);

    // 3) AC, BD (FFMA, merged single launch)
    acbd_kernel<<<dim3(8, 8, 16), 256>>>(wheads, rkp, rwb, rrb, acp, bdp);

    // 4a) scores + softmax -> fp16 P
    score_kernel<<<dim3(QLEN, BSZ), 256, SC_SMEM>>>(
        acp, bdp, masks, mproj, Pp);

    // 4b) V transpose-convert (fp16 hi/lo)
    cvt_vt<<<dim3(QLEN / 32, BSZ * NHEAD), 256>>>(wheads, Vth, Vtl);

    // 4c) PV GEMM -> avec
    pv_gemm<<<dim3(QLEN / 128, BSZ * NHEAD), 256, PV_SMEM>>>(
        Pp, Vth, Vtl, avp);

    // 5) x = attn_vec @ W_o^T + w  (fp16 1-term HMMA, fused residual)
    cvt_h<<<(MROWS * DMODEL) / 1024, 256>>>(avp, Ap, MROWS * DMODEL);
    cvt_h<<<(DMODEL * DMODEL) / 1024, 256>>>(Wo, Bp, DMODEL * DMODEL);
    mma_gemm<<<dim3(DMODEL / 128, MROWS / 128), 256, GEMM_SMEM>>>(
        Ap, Bp, w, xp, DMODEL, DMODEL);

    // 6) LayerNorm -> out
    ln_kernel<<<MROWS, 256>>>(xp, gamma, beta, out);
}

// round 16
// speedup vs baseline: 2.7283x; 1.1488x over previous
#include <cuda_runtime.h>
#include <cuda_bf16.h>
#include <cuda_fp16.h>
#include <math.h>
#include <stdint.h>

#define QLEN   1024
#define BSZ    4
#define DMODEL 1024
#define NHEAD  16
#define GHEADS 2
#define DHEAD  64
#define QKD    128
#define QKVOUT 1280
#define MROWS  4096
#define SCALE  0.125f
#define LN_EPS 1e-5f

// ---------------- scratch (device globals; no allocations allowed) ----------
__device__ float g_wheads[MROWS * QKVOUT];
__device__ float g_rk[QLEN * QKD];
__device__ float g_AC[BSZ * GHEADS * QLEN * QLEN];
__device__ float g_BD[BSZ * GHEADS * QLEN * QLEN];
__device__ float g_x[MROWS * DMODEL];

// fp16 GEMM operands (single-term A and B)
__device__ __half g_hA[MROWS * DMODEL];
__device__ __half g_hB[QKVOUT * DMODEL];

// acbd fp16 operands, contiguous [bg][row][64]
__device__ __half g_Qrw[8 * QLEN * DHEAD];
__device__ __half g_Qrr[8 * QLEN * DHEAD];
__device__ __half g_Kw[8 * QLEN * DHEAD];
__device__ __half g_rkw[2 * QLEN * DHEAD];

// normalized probabilities, single fp16: [b][h][i][j]  (134 MB)
__device__ __half g_P[BSZ * NHEAD * QLEN * QLEN];
// V transposed [b][h][d][j], fp16 hi/lo
__device__ __half g_Vthi[BSZ * NHEAD * DHEAD * QLEN];
__device__ __half g_Vtlo[BSZ * NHEAD * DHEAD * QLEN];

// ---------------- helpers ----------------------------------------------------
__device__ __forceinline__ uint32_t smem_u32(const void* p) {
    uint32_t a;
    asm("{ .reg .u64 t; cvta.to.shared.u64 t, %1; cvt.u32.u64 %0, t; }"
        : "=r"(a) : "l"(p));
    return a;
}
__device__ __forceinline__ void ldm4(uint32_t* r, uint32_t addr) {
    asm volatile("ldmatrix.sync.aligned.m8n8.x4.shared.b16 {%0,%1,%2,%3}, [%4];"
                 : "=r"(r[0]), "=r"(r[1]), "=r"(r[2]), "=r"(r[3]) : "r"(addr));
}
__device__ __forceinline__ void mma16816h(float* c, const uint32_t* a,
                                          uint32_t b0, uint32_t b1) {
    asm volatile(
        "mma.sync.aligned.m16n8k16.row.col.f32.f16.f16.f32 "
        "{%0,%1,%2,%3}, {%4,%5,%6,%7}, {%8,%9}, {%0,%1,%2,%3};"
        : "+f"(c[0]), "+f"(c[1]), "+f"(c[2]), "+f"(c[3])
        : "r"(a[0]), "r"(a[1]), "r"(a[2]), "r"(a[3]), "r"(b0), "r"(b1));
}
__device__ __forceinline__ void cp16(uint32_t saddr, const void* gaddr) {
    asm volatile("cp.async.cg.shared.global [%0], [%1], 16;\n"
                 :: "r"(saddr), "l"(gaddr) : "memory");
}

// ---------------- fp32 -> fp16 single ----------------------------------------
__global__ void __launch_bounds__(256) cvt_h(
    const float* __restrict__ x, __half* __restrict__ o, int n)
{
    int i = (blockIdx.x * 256 + threadIdx.x) * 4;
    if (i >= n) return;
    float4 v = *(const float4*)(x + i);
    union { __half b[4]; uint2 u; } H;
    H.b[0] = __float2half_rn(v.x);
    H.b[1] = __float2half_rn(v.y);
    H.b[2] = __float2half_rn(v.z);
    H.b[3] = __float2half_rn(v.w);
    *(uint2*)(o + i) = H.u;
}

// ---------------- acbd operand conversion (single fp16) ----------------------
__global__ void __launch_bounds__(512) cvt_qk(
    const float* __restrict__ wheads,
    const float* __restrict__ rwb, const float* __restrict__ rrb,
    __half* __restrict__ Qrw, __half* __restrict__ Qrr, __half* __restrict__ Kw)
{
    const int i = blockIdx.x;
    const int t = threadIdx.x;
    const int bg = t >> 6, d = t & 63;
    const int b = bg >> 1, g = bg & 1;
    const size_t src = (size_t)(i * BSZ + b) * QKVOUT + g * 64 + d;
    const size_t dst = (size_t)bg * QLEN * 64 + (size_t)i * 64 + d;

    float q = wheads[src];
    float k = wheads[src + QKD];
    Qrw[dst] = __float2half_rn(q + rwb[g * 64 + d]);
    Qrr[dst] = __float2half_rn(q + rrb[g * 64 + d]);
    Kw[dst]  = __float2half_rn(k);
}

__global__ void __launch_bounds__(128) cvt_rk(
    const float* __restrict__ rk, __half* __restrict__ rkw)
{
    const int i = blockIdx.x;
    const int t = threadIdx.x;            // g*64+d
    const int g = t >> 6, d = t & 63;
    rkw[(size_t)g * QLEN * 64 + (size_t)i * 64 + d] =
        __float2half_rn(rk[(size_t)i * QKD + t]);
}

// ---------------- fp16 1-term NT GEMM, cp.async double-buffered -------------
#define LDSB  40
#define TILEE (128 * LDSB)
#define GEMM_SMEM (2 * 2 * TILEE * 2)      // 40960 bytes

__global__ void __launch_bounds__(256) mma_gemm(
    const __half* __restrict__ A, const __half* __restrict__ B,
    const float* __restrict__ Dres, float* __restrict__ C, int N_, int K)
{
    extern __shared__ __half gsm[];
    const uint32_t sbase = smem_u32(gsm);

    const int t = threadIdx.x;
    const int warp = t >> 5, lane = t & 31;
    const int wm = warp >> 2, wn = warp & 3;
    const int m0 = blockIdx.y * 128, n0 = blockIdx.x * 128;

    float acc[4][4][4];
    #pragma unroll
    for (int i = 0; i < 4; i++)
        #pragma unroll
        for (int j = 0; j < 4; j++)
            #pragma unroll
            for (int u = 0; u < 4; u++) acc[i][j][u] = 0.f;

    const int lrow = t >> 2;
    const int lseg = (t & 3) * 8;

    const __half* mat[2];
    mat[0] = A + (size_t)m0 * K;
    mat[1] = B + (size_t)n0 * K;

    const uint32_t so_b = ((uint32_t)lrow * LDSB + lseg) * 2;
    const uint32_t so_b2 = so_b + (uint32_t)64 * LDSB * 2;

    const uint32_t a_lane =
        ((uint32_t)(wm * 64 + (lane & 15)) * LDSB + (lane >> 4) * 8) * 2;
    const uint32_t b_lane =
        ((uint32_t)(wn * 32 + (lane & 7) + (lane >> 4) * 8) * LDSB +
         ((lane >> 3) & 1) * 8) * 2;

    const int NCH = K >> 5;

    #pragma unroll
    for (int mi = 0; mi < 2; mi++) {
        const uint32_t mb = sbase + (uint32_t)mi * TILEE * 2;
        cp16(mb + so_b,  mat[mi] + (size_t)lrow * K + lseg);
        cp16(mb + so_b2, mat[mi] + (size_t)(lrow + 64) * K + lseg);
    }
    asm volatile("cp.async.commit_group;\n");

    for (int c = 0; c < NCH; c++) {
        if (c + 1 < NCH) {
            const int k0 = (c + 1) << 5;
            const uint32_t stoff = (uint32_t)(((c + 1) & 1) * 2) * TILEE * 2;
            #pragma unroll
            for (int mi = 0; mi < 2; mi++) {
                const uint32_t mb = sbase + stoff + (uint32_t)mi * TILEE * 2;
                cp16(mb + so_b,  mat[mi] + (size_t)lrow * K + k0 + lseg);
                cp16(mb + so_b2, mat[mi] + (size_t)(lrow + 64) * K + k0 + lseg);
            }
            asm volatile("cp.async.commit_group;\n");
            asm volatile("cp.async.wait_group 1;\n");
        } else {
            asm volatile("cp.async.wait_group 0;\n");
        }
        __syncthreads();

        const uint32_t stoff = (uint32_t)((c & 1) * 2) * TILEE * 2;
        const uint32_t bA = sbase + stoff;
        const uint32_t bB = bA + TILEE * 2;

        #pragma unroll
        for (int s = 0; s < 2; s++) {
            const uint32_t ko = s * 32;
            uint32_t ah[4][4], bb[2][4];
            #pragma unroll
            for (int mf = 0; mf < 4; mf++)
                ldm4(ah[mf], bA + a_lane + mf * 1280 + ko);
            #pragma unroll
            for (int np = 0; np < 2; np++)
                ldm4(bb[np], bB + b_lane + np * 1280 + ko);
            #pragma unroll
            for (int mf = 0; mf < 4; mf++) {
                #pragma unroll
                for (int nf = 0; nf < 4; nf++) {
                    const int np = nf >> 1, h = (nf & 1) * 2;
                    mma16816h(acc[mf][nf], ah[mf], bb[np][h], bb[np][h + 1]);
                }
            }
        }
        __syncthreads();
    }

    const int crow0 = m0 + wm * 64 + (lane >> 2);
    const int ccol0 = n0 + wn * 32 + (lane & 3) * 2;
    #pragma unroll
    for (int mf = 0; mf < 4; mf++) {
        #pragma unroll
        for (int nf = 0; nf < 4; nf++) {
            const int gr = crow0 + mf * 16;
            const int gc = ccol0 + nf * 8;
            float2 v0 = make_float2(acc[mf][nf][0], acc[mf][nf][1]);
            float2 v1 = make_float2(acc[mf][nf][2], acc[mf][nf][3]);
            if (Dres) {
                float2 d0 = *(const float2*)(Dres + (size_t)gr * N_ + gc);
                float2 d1 = *(const float2*)(Dres + (size_t)(gr + 8) * N_ + gc);
                v0.x += d0.x; v0.y += d0.y;
                v1.x += d1.x; v1.y += d1.y;
            }
            *(float2*)(C + (size_t)gr * N_ + gc) = v0;
            *(float2*)(C + (size_t)(gr + 8) * N_ + gc) = v1;
        }
    }
}

// ---------------- acbd batched fp16 HMMA GEMM (K=64) ------------------------
// grid (8, 8, 16): z = mode*8 + bg. Same lean body as mma_gemm.
__global__ void __launch_bounds__(256) acbd_mma(
    const __half* __restrict__ Qrw, const __half* __restrict__ Qrr,
    const __half* __restrict__ Kw,  const __half* __restrict__ rkw,
    float* __restrict__ ACo, float* __restrict__ BDo)
{
    extern __shared__ __half gsm[];
    const uint32_t sbase = smem_u32(gsm);

    const int z = blockIdx.z;
    const int mode = z >> 3, bg = z & 7, g = bg & 1;
    const int K = 64;

    const __half* A = (mode ? Qrr : Qrw) + (size_t)bg * QLEN * 64;
    const __half* B = mode ? (rkw + (size_t)g * QLEN * 64)
                           : (Kw + (size_t)bg * QLEN * 64);
    float* C = (mode ? BDo : ACo) + (size_t)bg * QLEN * QLEN;

    const int t = threadIdx.x;
    const int warp = t >> 5, lane = t & 31;
    const int wm = warp >> 2, wn = warp & 3;
    const int m0 = blockIdx.y * 128, n0 = blockIdx.x * 128;

    float acc[4][4][4];
    #pragma unroll
    for (int i = 0; i < 4; i++)
        #pragma unroll
        for (int j = 0; j < 4; j++)
            #pragma unroll
            for (int u = 0; u < 4; u++) acc[i][j][u] = 0.f;

    const int lrow = t >> 2;
    const int lseg = (t & 3) * 8;

    const __half* mat[2];
    mat[0] = A + (size_t)m0 * K;
    mat[1] = B + (size_t)n0 * K;

    const uint32_t so_b = ((uint32_t)lrow * LDSB + lseg) * 2;
    const uint32_t so_b2 = so_b + (uint32_t)64 * LDSB * 2;

    const uint32_t a_lane =
        ((uint32_t)(wm * 64 + (lane & 15)) * LDSB + (lane >> 4) * 8) * 2;
    const uint32_t b_lane =
        ((uint32_t)(wn * 32 + (lane & 7) + (lane >> 4) * 8) * LDSB +
         ((lane >> 3) & 1) * 8) * 2;

    #pragma unroll
    for (int mi = 0; mi < 2; mi++) {
        const uint32_t mb = sbase + (uint32_t)mi * TILEE * 2;
        cp16(mb + so_b,  mat[mi] + (size_t)lrow * K + lseg);
        cp16(mb + so_b2, mat[mi] + (size_t)(lrow + 64) * K + lseg);
    }
    asm volatile("cp.async.commit_group;\n");

    #pragma unroll
    for (int c = 0; c < 2; c++) {
        if (c == 0) {
            const uint32_t stoff = (uint32_t)2 * TILEE * 2;
            #pragma unroll
            for (int mi = 0; mi < 2; mi++) {
                const uint32_t mb = sbase + stoff + (uint32_t)mi * TILEE * 2;
                cp16(mb + so_b,  mat[mi] + (size_t)lrow * K + 32 + lseg);
                cp16(mb + so_b2, mat[mi] + (size_t)(lrow + 64) * K + 32 + lseg);
            }
            asm volatile("cp.async.commit_group;\n");
            asm volatile("cp.async.wait_group 1;\n");
        } else {
            asm volatile("cp.async.wait_group 0;\n");
        }
        __syncthreads();

        const uint32_t stoff = (uint32_t)((c & 1) * 2) * TILEE * 2;
        const uint32_t bA = sbase + stoff;
        const uint32_t bB = bA + TILEE * 2;

        #pragma unroll
        for (int s = 0; s < 2; s++) {
            const uint32_t ko = s * 32;
            uint32_t ah[4][4], bb[2][4];
            #pragma unroll
            for (int mf = 0; mf < 4; mf++)
                ldm4(ah[mf], bA + a_lane + mf * 1280 + ko);
            #pragma unroll
            for (int np = 0; np < 2; np++)
                ldm4(bb[np], bB + b_lane + np * 1280 + ko);
            #pragma unroll
            for (int mf = 0; mf < 4; mf++) {
                #pragma unroll
                for (int nf = 0; nf < 4; nf++) {
                    const int np = nf >> 1, h = (nf & 1) * 2;
                    mma16816h(acc[mf][nf], ah[mf], bb[np][h], bb[np][h + 1]);
                }
            }
        }
        __syncthreads();
    }

    const int crow0 = m0 + wm * 64 + (lane >> 2);
    const int ccol0 = n0 + wn * 32 + (lane & 3) * 2;
    #pragma unroll
    for (int mf = 0; mf < 4; mf++) {
        #pragma unroll
        for (int nf = 0; nf < 4; nf++) {
            const int gr = crow0 + mf * 16;
            const int gc = ccol0 + nf * 8;
            *(float2*)(C + (size_t)gr * QLEN + gc) =
                make_float2(acc[mf][nf][0], acc[mf][nf][1]);
            *(float2*)(C + (size_t)(gr + 8) * QLEN + gc) =
                make_float2(acc[mf][nf][2], acc[mf][nf][3]);
        }
    }
}

// ---------------- score + rel_shift + mask + softmax -> fp16 P --------------
#define SC_SMEM (16 * 1024 * 4)

__global__ void __launch_bounds__(256) score_kernel(
    const float* __restrict__ AC, const float* __restrict__ BD,
    const float* __restrict__ masks, const float* __restrict__ mproj,
    __half* __restrict__ P)
{
    extern __shared__ float S[];              // [16][1024]
    const int i = blockIdx.x, b = blockIdx.y;
    const int t = threadIdx.x;
    const int warp = t >> 5, lane = t & 31;

    float mp0[16], mp1[16], mp2[16];
    #pragma unroll
    for (int h = 0; h < 16; h++) {
        mp0[h] = mproj[h];
        mp1[h] = mproj[16 + h];
        mp2[h] = mproj[32 + h];
    }

    const float* ac0r = AC + ((size_t)(b * 2 + 0) * QLEN + i) * QLEN;
    const float* ac1r = AC + ((size_t)(b * 2 + 1) * QLEN + i) * QLEN;
    const float* bd0b = BD + (size_t)(b * 2 + 0) * QLEN * QLEN;
    const float* bd1b = BD + (size_t)(b * 2 + 1) * QLEN * QLEN;

    #pragma unroll
    for (int k = 0; k < 4; k++) {
        const int j = t + k * 256;
        float ac0 = ac0r[j], ac1 = ac1r[j];
        unsigned s  = (unsigned)(i + 1) * 1024u + (unsigned)j;
        unsigned i2 = s / 1025u;
        unsigned j2 = s - i2 * 1025u;
        float bd0 = 0.f, bd1 = 0.f;
        if (j2) {
            bd0 = bd0b[(size_t)i2 * QLEN + (j2 - 1u)];
            bd1 = bd1b[(size_t)i2 * QLEN + (j2 - 1u)];
        }
        const float* mr = masks + ((size_t)i * QLEN + j) * 3;
        float m0 = mr[0], m1 = mr[1], m2 = mr[2];
        float base0 = (ac0 + bd0) * SCALE;
        float base1 = (ac1 + bd1) * SCALE;
        #pragma unroll
        for (int h = 0; h < 8; h++) {
            float mw = m0 * mp0[h] + m1 * mp1[h] + m2 * mp2[h];
            S[h * 1024 + j] = base0 * mw;
        }
        #pragma unroll
        for (int h = 8; h < 16; h++) {
            float mw = m0 * mp0[h] + m1 * mp1[h] + m2 * mp2[h];
            S[h * 1024 + j] = base1 * mw;
        }
    }
    __syncthreads();

    #pragma unroll
    for (int hh = 0; hh < 2; hh++) {
        const int h = warp * 2 + hh;
        float* Sh = S + h * 1024;
        float mx = -1e30f;
        #pragma unroll 8
        for (int j = lane; j < 1024; j += 32) mx = fmaxf(mx, Sh[j]);
        #pragma unroll
        for (int o = 16; o > 0; o >>= 1)
            mx = fmaxf(mx, __shfl_xor_sync(0xffffffffu, mx, o));
        float sum = 0.f;
        #pragma unroll 8
        for (int j = lane; j < 1024; j += 32) {
            float e = __expf(Sh[j] - mx);
            Sh[j] = e;
            sum += e;
        }
        #pragma unroll
        for (int o = 16; o > 0; o >>= 1)
            sum += __shfl_xor_sync(0xffffffffu, sum, o);
        const float inv = 1.f / sum;
        __half* ph = P + ((size_t)(b * 16 + h) * QLEN + i) * QLEN;
        #pragma unroll 8
        for (int j = lane; j < 1024; j += 32)
            ph[j] = __float2half_rn(Sh[j] * inv);
    }
}

// ---------------- V transpose-convert: wheads -> Vt[b][h][d][j] fp16 --------
__global__ void __launch_bounds__(256) cvt_vt(
    const float* __restrict__ wheads,
    __half* __restrict__ Vthi, __half* __restrict__ Vtlo)
{
    __shared__ float sm[64 * 33];
    const int bh = blockIdx.y;
    const int b = bh >> 4, h = bh & 15;
    const int j0 = blockIdx.x * 32;
    const int t = threadIdx.x;

    #pragma unroll
    for (int k = 0; k < 8; k++) {
        int idx = t + k * 256;
        int j = idx >> 6, d = idx & 63;
        sm[d * 33 + j] = wheads[(size_t)(j0 + j) * (BSZ * QKVOUT) +
                                b * QKVOUT + 2 * QKD + h * 64 + d];
    }
    __syncthreads();
    #pragma unroll
    for (int k = 0; k < 8; k++) {
        int idx = t + k * 256;
        int d = idx >> 5, j = idx & 31;
        float v = sm[d * 33 + j];
        __half hi = __float2half_rn(v);
        size_t o = ((size_t)(bh * 64 + d)) * QLEN + j0 + j;
        Vthi[o] = hi;
        Vtlo[o] = __float2half_rn(v - __half2float(hi));
    }
}

// ---------------- PV GEMM: writes fp16 avec directly into gemm3's A ---------
#define PV_TILEA (128 * LDSB)
#define PV_TILEB (64 * LDSB)
#define PV_STAGE (PV_TILEA + 2 * PV_TILEB)
#define PV_SMEM  (2 * PV_STAGE * 2)

__global__ void __launch_bounds__(256) pv_gemm(
    const __half* __restrict__ P,
    const __half* __restrict__ Vthi, const __half* __restrict__ Vtlo,
    __half* __restrict__ avecH)
{
    extern __shared__ __half psm[];
    const uint32_t sbase = smem_u32(psm);
    const int bh = blockIdx.y;
    const int b = bh >> 4, h = bh & 15;
    const int i0 = blockIdx.x * 128;
    const int t = threadIdx.x;
    const int warp = t >> 5, lane = t & 31;
    const int wm = warp >> 1, wn = warp & 1;

    float acc[2][4][4];
    #pragma unroll
    for (int i = 0; i < 2; i++)
        #pragma unroll
        for (int j = 0; j < 4; j++)
            #pragma unroll
            for (int u = 0; u < 4; u++) acc[i][j][u] = 0.f;

    const __half* pA = P + ((size_t)bh * QLEN + i0) * QLEN;
    const __half* pB[2];
    pB[0] = Vthi + (size_t)bh * 64 * QLEN;
    pB[1] = Vtlo + (size_t)bh * 64 * QLEN;

    const int arow = t >> 1;
    const int aoff = (t & 1) * 16;
    const int vrow = (t & 127) >> 1;
    const int voff = (t & 1) * 16;

    const uint32_t a_lane =
        ((uint32_t)(wm * 32 + (lane & 15)) * LDSB + (lane >> 4) * 8) * 2;
    const uint32_t b_lane =
        ((uint32_t)(wn * 32 + (lane & 7) + (lane >> 4) * 8) * LDSB +
         ((lane >> 3) & 1) * 8) * 2;

    // prologue stage 0
    {
        const uint32_t so = ((uint32_t)arow * LDSB + aoff) * 2;
        cp16(sbase + so,      pA + (size_t)arow * QLEN + aoff);
        cp16(sbase + so + 16, pA + (size_t)arow * QLEN + aoff + 8);
        if (t < 128) {
            #pragma unroll
            for (int m = 0; m < 2; m++) {
                const uint32_t mb = sbase +
                    (uint32_t)(PV_TILEA + m * PV_TILEB) * 2;
                const uint32_t sv = ((uint32_t)vrow * LDSB + voff) * 2;
                cp16(mb + sv,      pB[m] + (size_t)vrow * QLEN + voff);
                cp16(mb + sv + 16, pB[m] + (size_t)vrow * QLEN + voff + 8);
            }
        }
        asm volatile("cp.async.commit_group;\n");
    }

    const int NCH = QLEN >> 5;
    for (int c = 0; c < NCH; c++) {
        if (c + 1 < NCH) {
            const int k0 = (c + 1) << 5;
            const uint32_t stoff = (uint32_t)(((c + 1) & 1) * PV_STAGE) * 2;
            const uint32_t so = ((uint32_t)arow * LDSB + aoff) * 2;
            cp16(sbase + stoff + so,      pA + (size_t)arow * QLEN + k0 + aoff);
            cp16(sbase + stoff + so + 16, pA + (size_t)arow * QLEN + k0 + aoff + 8);
            if (t < 128) {
                #pragma unroll
                for (int m = 0; m < 2; m++) {
                    const uint32_t mb = sbase + stoff +
                        (uint32_t)(PV_TILEA + m * PV_TILEB) * 2;
                    const uint32_t sv = ((uint32_t)vrow * LDSB + voff) * 2;
                    cp16(mb + sv,      pB[m] + (size_t)vrow * QLEN + k0 + voff);
                    cp16(mb + sv + 16, pB[m] + (size_t)vrow * QLEN + k0 + voff + 8);
                }
            }
            asm volatile("cp.async.commit_group;\n");
            asm volatile("cp.async.wait_group 1;\n");
        } else {
            asm volatile("cp.async.wait_group 0;\n");
        }
        __syncthreads();

        const uint32_t stoff = (uint32_t)((c & 1) * PV_STAGE) * 2;
        const uint32_t bP  = sbase + stoff;
        const uint32_t bVh = bP + (uint32_t)PV_TILEA * 2;
        const uint32_t bVl = bVh + (uint32_t)PV_TILEB * 2;

        #pragma unroll
        for (int s = 0; s < 2; s++) {
            const uint32_t ko = s * 32;
            uint32_t ap[2][4], vh[2][4], vl[2][4];
            #pragma unroll
            for (int mf = 0; mf < 2; mf++)
                ldm4(ap[mf], bP + a_lane + mf * 1280 + ko);
            #pragma unroll
            for (int np = 0; np < 2; np++) {
                ldm4(vh[np], bVh + b_lane + np * 1280 + ko);
                ldm4(vl[np], bVl + b_lane + np * 1280 + ko);
            }
            #pragma unroll
            for (int mf = 0; mf < 2; mf++) {
                #pragma unroll
                for (int nf = 0; nf < 4; nf++) {
                    const int np = nf >> 1, hb = (nf & 1) * 2;
                    mma16816h(acc[mf][nf], ap[mf], vh[np][hb], vh[np][hb + 1]);
                    mma16816h(acc[mf][nf], ap[mf], vl[np][hb], vl[np][hb + 1]);
                }
            }
        }
        __syncthreads();
    }

    // epilogue: write fp16 into avecH[(i*4+b)][h*64+d] (gemm3 A layout)
    const int rloc0 = wm * 32 + (lane >> 2);
    const int col0  = wn * 32 + (lane & 3) * 2;
    #pragma unroll
    for (int mf = 0; mf < 2; mf++) {
        #pragma unroll
        for (int nf = 0; nf < 4; nf++) {
            const int gr0 = i0 + rloc0 + mf * 16;
            const int gc  = col0 + nf * 8;
            __half2 h0 = __floats2half2_rn(acc[mf][nf][0], acc[mf][nf][1]);
            __half2 h1 = __floats2half2_rn(acc[mf][nf][2], acc[mf][nf][3]);
            *(__half2*)(avecH + ((size_t)(gr0 * BSZ + b)) * DMODEL + h * 64 + gc) = h0;
            *(__half2*)(avecH + ((size_t)((gr0 + 8) * BSZ + b)) * DMODEL + h * 64 + gc) = h1;
        }
    }
}

// ---------------- LayerNorm --------------------------------------------------
__global__ void __launch_bounds__(256) ln_kernel(
    const float* __restrict__ X, const float* __restrict__ gamma,
    const float* __restrict__ beta, float* __restrict__ out)
{
    const int row = blockIdx.x;
    const int t = threadIdx.x;
    const float4* x4 = (const float4*)(X + (size_t)row * DMODEL);
    float4 v = x4[t];
    float s  = v.x + v.y + v.z + v.w;
    float sq = v.x * v.x + v.y * v.y + v.z * v.z + v.w * v.w;
    #pragma unroll
    for (int o = 16; o > 0; o >>= 1) {
        s  += __shfl_xor_sync(0xffffffffu, s,  o);
        sq += __shfl_xor_sync(0xffffffffu, sq, o);
    }
    __shared__ float ssum[8], ssq[8];
    __shared__ float smu, srstd;
    if ((t & 31) == 0) { ssum[t >> 5] = s; ssq[t >> 5] = sq; }
    __syncthreads();
    if (t == 0) {
        float ts = 0.f, tq = 0.f;
        #pragma unroll
        for (int k = 0; k < 8; k++) { ts += ssum[k]; tq += ssq[k]; }
        float mu = ts * (1.f / DMODEL);
        float var = tq * (1.f / DMODEL) - mu * mu;
        smu = mu;
        srstd = rsqrtf(var + LN_EPS);
    }
    __syncthreads();
    float mu = smu, rstd = srstd;
    float4 gm = ((const float4*)gamma)[t];
    float4 bt = ((const float4*)beta)[t];
    float4 o;
    o.x = (v.x - mu) * rstd * gm.x + bt.x;
    o.y = (v.y - mu) * rstd * gm.y + bt.y;
    o.z = (v.z - mu) * rstd * gm.z + bt.z;
    o.w = (v.w - mu) * rstd * gm.w + bt.w;
    ((float4*)(out + (size_t)row * DMODEL))[t] = o;
}

// ---------------- launch ----------------------------------------------------
extern "C" void kernel_launch(void* const* d_in, const int* in_sizes, int n_in,
                              void* d_out, int out_size)
{
    const float* w     = (const float*)d_in[0];
    const float* r     = (const float*)d_in[1];
    const float* rwb   = (const float*)d_in[2];
    const float* rrb   = (const float*)d_in[3];
    const float* masks = (const float*)d_in[4];
    const float* Wqkv  = (const float*)d_in[5];
    const float* Wr    = (const float*)d_in[6];
    const float* mproj = (const float*)d_in[7];
    const float* Wo    = (const float*)d_in[8];
    const float* gamma = (const float*)d_in[9];
    const float* beta  = (const float*)d_in[10];
    float* out = (float*)d_out;

    float *wheads, *rkp, *acp, *bdp, *xp;
    cudaGetSymbolAddress((void**)&wheads, g_wheads);
    cudaGetSymbolAddress((void**)&rkp,    g_rk);
    cudaGetSymbolAddress((void**)&acp,    g_AC);
    cudaGetSymbolAddress((void**)&bdp,    g_BD);
    cudaGetSymbolAddress((void**)&xp,     g_x);

    __half *Ap, *Bp, *Pp, *Vth, *Vtl, *Qrw, *Qrr, *Kw, *rkw;
    cudaGetSymbolAddress((void**)&Ap,  g_hA);
    cudaGetSymbolAddress((void**)&Bp,  g_hB);
    cudaGetSymbolAddress((void**)&Pp,  g_P);
    cudaGetSymbolAddress((void**)&Vth, g_Vthi);
    cudaGetSymbolAddress((void**)&Vtl, g_Vtlo);
    cudaGetSymbolAddress((void**)&Qrw, g_Qrw);
    cudaGetSymbolAddress((void**)&Qrr, g_Qrr);
    cudaGetSymbolAddress((void**)&Kw,  g_Kw);
    cudaGetSymbolAddress((void**)&rkw, g_rkw);

    cudaFuncSetAttribute(mma_gemm,
                         cudaFuncAttributeMaxDynamicSharedMemorySize, GEMM_SMEM);
    cudaFuncSetAttribute(acbd_mma,
                         cudaFuncAttributeMaxDynamicSharedMemorySize, GEMM_SMEM);
    cudaFuncSetAttribute(score_kernel,
                         cudaFuncAttributeMaxDynamicSharedMemorySize, SC_SMEM);
    cudaFuncSetAttribute(pv_gemm,
                         cudaFuncAttributeMaxDynamicSharedMemorySize, PV_SMEM);

    // 1) w_heads = w @ W_qkv^T  (fp16 1-term HMMA)
    cvt_h<<<(MROWS * DMODEL) / 1024, 256>>>(w, Ap, MROWS * DMODEL);
    cvt_h<<<(QKVOUT * DMODEL) / 1024, 256>>>(Wqkv, Bp, QKVOUT * DMODEL);
    mma_gemm<<<dim3(QKVOUT / 128, MROWS / 128), 256, GEMM_SMEM>>>(
        Ap, Bp, nullptr, wheads, QKVOUT, DMODEL);

    // 2) r_head_k = r @ W_r^T
    cvt_h<<<(QLEN * DMODEL) / 1024, 256>>>(r, Ap, QLEN * DMODEL);
    cvt_h<<<(QKD * DMODEL) / 1024, 256>>>(Wr, Bp, QKD * DMODEL);
    mma_gemm<<<dim3(QKD / 128, QLEN / 128), 256, GEMM_SMEM>>>(
        Ap, Bp, nullptr, rkp, QKD, DMODEL);

    // 3) AC, BD via lean fp16 HMMA
    cvt_qk<<<QLEN, 512>>>(wheads, rwb, rrb, Qrw, Qrr, Kw);
    cvt_rk<<<QLEN, 128>>>(rkp, rkw);
    acbd_mma<<<dim3(8, 8, 16), 256, GEMM_SMEM>>>(
        Qrw, Qrr, Kw, rkw, acp, bdp);

    // 4a) scores + softmax -> fp16 P
    score_kernel<<<dim3(QLEN, BSZ), 256, SC_SMEM>>>(
        acp, bdp, masks, mproj, Pp);

    // 4b) V transpose-convert (fp16 hi/lo)
    cvt_vt<<<dim3(QLEN / 32, BSZ * NHEAD), 256>>>(wheads, Vth, Vtl);

    // 4c) PV GEMM -> fp16 avec (directly into gemm3's A buffer)
    pv_gemm<<<dim3(QLEN / 128, BSZ * NHEAD), 256, PV_SMEM>>>(
        Pp, Vth, Vtl, Ap);

    // 5) x = attn_vec @ W_o^T + w  (fp16 1-term HMMA, fused residual)
    cvt_h<<<(DMODEL * DMODEL) / 1024, 256>>>(Wo, Bp, DMODEL * DMODEL);
    mma_gemm<<<dim3(DMODEL / 128, MROWS / 128), 256, GEMM_SMEM>>>(
        Ap, Bp, w, xp, DMODEL, DMODEL);

    // 6) LayerNorm -> out
    ln_kernel<<<MROWS, 256>>>(xp, gamma, beta, out);
}